// round 15
// baseline (speedup 1.0000x reference)
#include <cuda_runtime.h>
#include <cuda_bf16.h>
#include <cstdint>
#include <math.h>

#define NT   16384
#define GN   128
#define DD   128
#define HN   4
#define DHD  32
#define NBLK 10
#define MAXL 256
#define EPSV 1e-5f

typedef __nv_bfloat16 bf16;

// ---------------- scratch ----------------
__device__ float g_x  [NT * DD];
__device__ bf16  g_qh [NT * 3 * DD];
__device__ bf16  g_ql [NT * 3 * DD];
__device__ bf16  g_yh [NT * DD];
__device__ bf16  g_yl [NT * DD];
__device__ bf16  g_ah [NT * DD];
__device__ bf16  g_al [NT * DD];
__device__ bf16  g_mh [NT * 4 * DD];
__device__ bf16  g_ml [NT * 4 * DD];
__device__ float g_bn_mean[16];
__device__ float g_bn_rstd[16];
__device__ int   g_seg[GN + 1];

__device__ bf16 g_wq_hi [NBLK * 384 * 128];
__device__ bf16 g_wq_lo [NBLK * 384 * 128];
__device__ bf16 g_wo_hi [NBLK * 128 * 128];
__device__ bf16 g_wo_lo [NBLK * 128 * 128];
__device__ bf16 g_wm1_hi[NBLK * 512 * 128];
__device__ bf16 g_wm1_lo[NBLK * 512 * 128];
__device__ bf16 g_wm2_hi[NBLK * 128 * 512];
__device__ bf16 g_wm2_lo[NBLK * 128 * 512];

// ---------------- asm helpers ----------------
__device__ __forceinline__ uint32_t smem_u32(const void* p) {
    uint32_t a;
    asm("{ .reg .u64 t; cvta.to.shared.u64 t, %1; cvt.u32.u64 %0, t; }" : "=r"(a) : "l"(p));
    return a;
}
__device__ __forceinline__ void cp16(uint32_t dst, const void* src) {
    asm volatile("cp.async.cg.shared.global [%0], [%1], 16;" :: "r"(dst), "l"(src));
}
#define CP_COMMIT() asm volatile("cp.async.commit_group;" ::: "memory")
#define CP_WAIT(n)  asm volatile("cp.async.wait_group %0;" :: "n"(n) : "memory")

__device__ __forceinline__ void ldm_x4(uint32_t r[4], uint32_t a) {
    asm volatile("ldmatrix.sync.aligned.m8n8.x4.shared.b16 {%0,%1,%2,%3}, [%4];"
                 : "=r"(r[0]), "=r"(r[1]), "=r"(r[2]), "=r"(r[3]) : "r"(a));
}
__device__ __forceinline__ void ldm_x4_t(uint32_t r[4], uint32_t a) {
    asm volatile("ldmatrix.sync.aligned.m8n8.x4.trans.shared.b16 {%0,%1,%2,%3}, [%4];"
                 : "=r"(r[0]), "=r"(r[1]), "=r"(r[2]), "=r"(r[3]) : "r"(a));
}
__device__ __forceinline__ void mma_bf16(float c[4], const uint32_t a[4],
                                         uint32_t b0, uint32_t b1) {
    asm volatile(
        "mma.sync.aligned.m16n8k16.row.col.f32.bf16.bf16.f32 "
        "{%0,%1,%2,%3}, {%4,%5,%6,%7}, {%8,%9}, {%0,%1,%2,%3};"
        : "+f"(c[0]), "+f"(c[1]), "+f"(c[2]), "+f"(c[3])
        : "r"(a[0]), "r"(a[1]), "r"(a[2]), "r"(a[3]), "r"(b0), "r"(b1));
}

__device__ __forceinline__ void split_bf16(float v, bf16& hi, bf16& lo) {
    hi = __float2bfloat16(v);
    lo = __float2bfloat16(v - __bfloat162float(hi));
}
__device__ __forceinline__ uint32_t pack2(bf16 a, bf16 b) {
    __nv_bfloat162 t = {a, b};
    return *(uint32_t*)&t;
}
__device__ __forceinline__ float fast_gelu(float u) {
    float z = 0.7978845608028654f * (u + 0.044715f * u * u * u);
    float t = 1.f - 2.f / (__expf(2.f * z) + 1.f);
    return 0.5f * u * (1.f + t);
}

// ---------------- merged BN stats + segment offsets ----------------
__global__ void bnseg_kernel(const float* __restrict__ s, const float* __restrict__ v,
                             const int* __restrict__ bidx) {
    if (blockIdx.x < 16) {
        int f = blockIdx.x, t = threadIdx.x;
        float sum = 0.f, sq = 0.f;
        for (int i = t; i < NT; i += 256) {
            float x = (f < 13) ? s[i * 13 + f] : v[i * 3 + (f - 13)];
            sum += x; sq += x * x;
        }
        __shared__ float rs[256], rq[256];
        rs[t] = sum; rq[t] = sq;
        __syncthreads();
        for (int st = 128; st > 0; st >>= 1) {
            if (t < st) { rs[t] += rs[t + st]; rq[t] += rq[t + st]; }
            __syncthreads();
        }
        if (t == 0) {
            float m = rs[0] * (1.f / NT);
            float var = rq[0] * (1.f / NT) - m * m;
            g_bn_mean[f] = m;
            g_bn_rstd[f] = rsqrtf(var + EPSV);
        }
    } else {
        int g = threadIdx.x;
        if (g > GN) return;
        int lo = 0, hi = NT;
        while (lo < hi) {
            int mid = (lo + hi) >> 1;
            if (bidx[mid] < g) lo = mid + 1; else hi = mid;
        }
        g_seg[g] = lo;
    }
}

// ---------------- BN + embed + LN1[0], warp per row ----------------
__global__ __launch_bounds__(256)
void embed_ln_kernel(const float* __restrict__ s, const float* __restrict__ v,
                     const float* __restrict__ gamma, const float* __restrict__ beta,
                     const float* __restrict__ w_in, const float* __restrict__ b_in,
                     const float* __restrict__ gam, const float* __restrict__ bet) {
    int w = threadIdx.x >> 5, lane = threadIdx.x & 31;
    int row = blockIdx.x * 8 + w;
    float4 bi = *(const float4*)(b_in + lane * 4);
    float4 gv = *(const float4*)(gam + lane * 4);
    float4 bv = *(const float4*)(bet + lane * 4);
    float xr = 0.f, gmr = 0.f, btr = 0.f, mnr = 0.f, rsr = 0.f;
    if (lane < 16) {
        xr = (lane < 13) ? s[row * 13 + lane] : v[row * 3 + (lane - 13)];
        gmr = gamma[lane]; btr = beta[lane];
        mnr = g_bn_mean[lane]; rsr = g_bn_rstd[lane];
    }
    float xn = (xr - mnr) * rsr * gmr + btr;
    float acc[4] = {bi.x, bi.y, bi.z, bi.w};
#pragma unroll
    for (int k = 0; k < 16; k++) {
        float xk = __shfl_sync(0xffffffffu, xn, k);
        float4 wv = *(const float4*)(w_in + k * DD + lane * 4);
        acc[0] += xk * wv.x; acc[1] += xk * wv.y;
        acc[2] += xk * wv.z; acc[3] += xk * wv.w;
    }
    *(float4*)(g_x + (size_t)row * DD + lane * 4) = *(float4*)acc;
    float ssum = acc[0] + acc[1] + acc[2] + acc[3];
    float sqs = acc[0]*acc[0] + acc[1]*acc[1] + acc[2]*acc[2] + acc[3]*acc[3];
#pragma unroll
    for (int o = 16; o; o >>= 1) {
        ssum += __shfl_xor_sync(0xffffffffu, ssum, o);
        sqs  += __shfl_xor_sync(0xffffffffu, sqs,  o);
    }
    float m = ssum * (1.f / DD);
    float var = sqs * (1.f / DD) - m * m;
    float r = rsqrtf(var + EPSV);
    bf16 h[4], l[4];
    split_bf16((acc[0] - m) * r * gv.x + bv.x, h[0], l[0]);
    split_bf16((acc[1] - m) * r * gv.y + bv.y, h[1], l[1]);
    split_bf16((acc[2] - m) * r * gv.z + bv.z, h[2], l[2]);
    split_bf16((acc[3] - m) * r * gv.w + bv.w, h[3], l[3]);
    *(uint2*)(g_yh + (size_t)row * DD + lane * 4) = *(uint2*)h;
    *(uint2*)(g_yl + (size_t)row * DD + lane * 4) = *(uint2*)l;
}

// ---------------- merged weight prep ----------------
#define WQ_E (384 * 128)
#define WO_E (128 * 128)
#define W1_E (512 * 128)
#define W2_E (128 * 512)
__global__ void wprep_kernel(const float* __restrict__ wq, const float* __restrict__ wo,
                             const float* __restrict__ w1, const float* __restrict__ w2) {
    int idx = blockIdx.x * 256 + threadIdx.x;
    const float* w; bf16 *whi, *wlo; int K, N, li;
    if (idx < NBLK * WQ_E) {
        w = wq; whi = g_wq_hi; wlo = g_wq_lo; K = 128; N = 384; li = idx;
    } else if (idx < NBLK * (WQ_E + WO_E)) {
        w = wo; whi = g_wo_hi; wlo = g_wo_lo; K = 128; N = 128; li = idx - NBLK * WQ_E;
    } else if (idx < NBLK * (WQ_E + WO_E + W1_E)) {
        w = w1; whi = g_wm1_hi; wlo = g_wm1_lo; K = 128; N = 512; li = idx - NBLK * (WQ_E + WO_E);
    } else if (idx < NBLK * (WQ_E + WO_E + W1_E + W2_E)) {
        w = w2; whi = g_wm2_hi; wlo = g_wm2_lo; K = 512; N = 128; li = idx - NBLK * (WQ_E + WO_E + W1_E);
    } else return;
    int k = li % K;
    int n = (li / K) % N;
    int b = li / (K * N);
    float x = w[(size_t)b * K * N + (size_t)k * N + n];
    bf16 hi, lo;
    split_bf16(x, hi, lo);
    whi[li] = hi;
    wlo[li] = lo;
}

// ---------------- chunk-pipelined panel GEMM (single-sync loop) ----------------
// BM=64, BN=128. K in 64-wide chunks (128B rows), double-buffered.
// Per chunk h: WAIT(0) [chunk h landed; only group h in flight] -> ONE sync
// [chunk h visible to all + all warps done compute h-1, buffer free] ->
// stage(h+1) -> compute h barrier-free. 256 threads, 8 warps 2(m) x 4(n).
#define RS      144
#define CA_L    9216
#define CB_H    18432
#define CB_L    36864
#define CBUF    55296
#define GEMM_SMEM (2 * CBUF)   // 110592

template <int FUSE>
__global__ __launch_bounds__(256, 2)
void gemm_mma(const bf16* __restrict__ Ahi, const bf16* __restrict__ Alo,
              const bf16* __restrict__ Bhi, const bf16* __restrict__ Blo,
              const float* __restrict__ bias, const float* __restrict__ R,
              float* __restrict__ C, bf16* __restrict__ Chi, bf16* __restrict__ Clo,
              int K, int Nc,
              const float* __restrict__ lngam, const float* __restrict__ lnbet) {
    extern __shared__ char smem[];
    uint32_t sb = smem_u32(smem);
    int tid = threadIdx.x, lane = tid & 31, wid = tid >> 5;
    int wm = wid & 1, wn = wid >> 1;
    int m0 = blockIdx.y * 64, n0 = blockIdx.x * 128;

    int seg = tid & 7;
    int rowb = tid >> 3;                      // 0..31
    int scol = seg * 16;

    float acc[2][4][4];
#pragma unroll
    for (int i = 0; i < 2; i++)
#pragma unroll
        for (int j = 0; j < 4; j++)
#pragma unroll
            for (int q = 0; q < 4; q++) acc[i][j][q] = 0.f;

    uint32_t a_off = (uint32_t)((wm * 32 + (lane & 15)) * RS + ((lane >> 4) << 4));
    uint32_t b_lane = (uint32_t)((lane & 7) + ((lane >> 4) << 3));
    uint32_t b_half = ((lane >> 3) & 1) << 4;
    uint32_t b_off = (uint32_t)((wn * 32 + b_lane) * RS + b_half);

    int nh = K >> 6;

    auto stage = [&](int h, int b) {
        uint32_t base = sb + (uint32_t)b * CBUF;
        int kc = h << 6;
#pragma unroll
        for (int i = 0; i < 12; i++) {
            int rr = rowb + i * 32;            // 0..383
            uint32_t dst; const bf16* src;
            if (rr < 64) {
                dst = base + rr * RS;
                src = Ahi + (size_t)(m0 + rr) * K + kc;
            } else if (rr < 128) {
                int r = rr - 64;
                dst = base + CA_L + r * RS;
                src = Alo + (size_t)(m0 + r) * K + kc;
            } else if (rr < 256) {
                int r = rr - 128;
                dst = base + CB_H + r * RS;
                src = Bhi + (size_t)(n0 + r) * K + kc;
            } else {
                int r = rr - 256;
                dst = base + CB_L + r * RS;
                src = Blo + (size_t)(n0 + r) * K + kc;
            }
            cp16(dst + scol, (const char*)src + scol);
        }
    };

    stage(0, 0);
    CP_COMMIT();

    for (int h = 0; h < nh; h++) {
        CP_WAIT(0);                   // chunk h landed (only group in flight)
        __syncthreads();              // all warps: see chunk h AND finished compute h-1
        if (h + 1 < nh) {
            stage(h + 1, (h + 1) & 1);  // into buffer freed by compute h-1
            CP_COMMIT();
        }

        uint32_t base = sb + (uint32_t)(h & 1) * CBUF;
        uint32_t aB = base + a_off;
        uint32_t bB = base + CB_H + b_off;

#pragma unroll
        for (int s = 0; s < 4; s++) {
            uint32_t koff = (uint32_t)(s * 32);
            uint32_t ah[2][4], al[2][4];
#pragma unroll
            for (int mt = 0; mt < 2; mt++) {
                uint32_t addr = aB + mt * 16 * RS + koff;
                ldm_x4(ah[mt], addr);
                ldm_x4(al[mt], addr + CA_L);
            }
            uint32_t bh[4][2], bl[4][2];
#pragma unroll
            for (int g4 = 0; g4 < 2; g4++) {
                uint32_t addr = bB + g4 * 16 * RS + koff;
                uint32_t t4[4];
                ldm_x4(t4, addr);
                bh[g4 * 2][0] = t4[0]; bh[g4 * 2][1] = t4[1];
                bh[g4 * 2 + 1][0] = t4[2]; bh[g4 * 2 + 1][1] = t4[3];
                ldm_x4(t4, addr + (CB_L - CB_H));
                bl[g4 * 2][0] = t4[0]; bl[g4 * 2][1] = t4[1];
                bl[g4 * 2 + 1][0] = t4[2]; bl[g4 * 2 + 1][1] = t4[3];
            }
            // per-acc order hh -> hl -> lh preserved (bit-identical)
#pragma unroll
            for (int mt = 0; mt < 2; mt++)
#pragma unroll
                for (int nt = 0; nt < 4; nt++)
                    mma_bf16(acc[mt][nt], ah[mt], bh[nt][0], bh[nt][1]);
#pragma unroll
            for (int mt = 0; mt < 2; mt++)
#pragma unroll
                for (int nt = 0; nt < 4; nt++)
                    mma_bf16(acc[mt][nt], ah[mt], bl[nt][0], bl[nt][1]);
#pragma unroll
            for (int mt = 0; mt < 2; mt++)
#pragma unroll
                for (int nt = 0; nt < 4; nt++)
                    mma_bf16(acc[mt][nt], al[mt], bh[nt][0], bh[nt][1]);
        }
    }

    float* xbuf = (float*)smem;   // FUSE=4: [64][132] fp32 residual tile
    if (FUSE == 4) __syncthreads();

    int lane4 = lane >> 2, lanem = (lane & 3) * 2;
#pragma unroll
    for (int mt = 0; mt < 2; mt++) {
#pragma unroll
        for (int nt = 0; nt < 4; nt++) {
            int col = n0 + wn * 32 + nt * 8 + lanem;
            int r0 = m0 + wm * 32 + mt * 16 + lane4;
            float2 bb = *(const float2*)(bias + col);
#pragma unroll
            for (int half = 0; half < 2; half++) {
                int r = r0 + half * 8;
                float v0 = acc[mt][nt][half * 2 + 0] + bb.x;
                float v1 = acc[mt][nt][half * 2 + 1] + bb.y;
                size_t o = (size_t)r * Nc + col;
                if (FUSE == 1 || FUSE == 4) {
                    float2 rr = *(const float2*)(R + o);
                    v0 += rr.x; v1 += rr.y;
                }
                if (FUSE == 2 || FUSE == 3) {
                    if (FUSE == 2) {
                        v0 = fast_gelu(v0);
                        v1 = fast_gelu(v1);
                    }
                    bf16 h0, l0, h1, l1;
                    split_bf16(v0, h0, l0);
                    split_bf16(v1, h1, l1);
                    *(uint32_t*)(Chi + o) = pack2(h0, h1);
                    *(uint32_t*)(Clo + o) = pack2(l0, l1);
                } else {
                    float2 ov = {v0, v1};
                    *(float2*)(C + o) = ov;
                    if (FUSE == 4) {
                        xbuf[(r - m0) * 132 + col] = v0;
                        xbuf[(r - m0) * 132 + col + 1] = v1;
                    }
                }
            }
        }
    }

    if (FUSE == 4) {
        __syncthreads();
#pragma unroll
        for (int rr = wid; rr < 64; rr += 8) {
            float4 xv = *(float4*)(xbuf + rr * 132 + lane * 4);
            float s = xv.x + xv.y + xv.z + xv.w;
            float sq = xv.x*xv.x + xv.y*xv.y + xv.z*xv.z + xv.w*xv.w;
#pragma unroll
            for (int o = 16; o; o >>= 1) {
                s  += __shfl_xor_sync(0xffffffffu, s,  o);
                sq += __shfl_xor_sync(0xffffffffu, sq, o);
            }
            float m = s * (1.f / DD);
            float var = sq * (1.f / DD) - m * m;
            float rcp = rsqrtf(var + EPSV);
            float4 gv = *(const float4*)(lngam + lane * 4);
            float4 bv = *(const float4*)(lnbet + lane * 4);
            bf16 h[4], l[4];
            split_bf16((xv.x - m) * rcp * gv.x + bv.x, h[0], l[0]);
            split_bf16((xv.y - m) * rcp * gv.y + bv.y, h[1], l[1]);
            split_bf16((xv.z - m) * rcp * gv.z + bv.z, h[2], l[2]);
            split_bf16((xv.w - m) * rcp * gv.w + bv.w, h[3], l[3]);
            size_t off = (size_t)(m0 + rr) * DD + lane * 4;
            *(uint2*)(Chi + off) = *(uint2*)h;
            *(uint2*)(Clo + off) = *(uint2*)l;
        }
    }
}

// ---------------- flash segment attention (unchanged from R14) ----------------
#define AT_ROWB 80
#define AT_ARR  (MAXL * AT_ROWB)
#define AT_SMEM (4 * AT_ARR)

__global__ __launch_bounds__(256)
void attn_flash() {
    extern __shared__ char sm[];
    bf16* sKh = (bf16*)sm;
    bf16* sKl = (bf16*)(sm + AT_ARR);
    bf16* sVh = (bf16*)(sm + 2 * AT_ARR);
    bf16* sVl = (bf16*)(sm + 3 * AT_ARR);

    int g = blockIdx.x, h = blockIdx.y;
    int start = g_seg[g];
    int cnt = g_seg[g + 1] - start;
    if (cnt <= 0) return;
    if (cnt > MAXL) cnt = MAXL;
    int tid = threadIdx.x, lane = tid & 31, wid = tid >> 5;
    int tiles = (cnt + 15) >> 4;
    int ncols = tiles << 4;

    uint32_t aKh = smem_u32(sKh), aKl = smem_u32(sKl);
    uint32_t aVh = smem_u32(sVh), aVl = smem_u32(sVl);

    {
        uint4 z = {0, 0, 0, 0};
        int npad = (ncols - cnt) * 4;
        for (int idx = tid; idx < npad; idx += 256) {
            int j = cnt + (idx >> 2), c = idx & 3;
            int o = j * AT_ROWB + c * 16;
            *(uint4*)((char*)sKh + o) = z;
            *(uint4*)((char*)sKl + o) = z;
            *(uint4*)((char*)sVh + o) = z;
            *(uint4*)((char*)sVl + o) = z;
        }
    }
    for (int idx = tid; idx < cnt * 4; idx += 256) {
        int j = idx >> 2, c = idx & 3;
        size_t base = (size_t)(start + j) * 384 + h * 32 + c * 8;
        uint32_t d = (uint32_t)(j * AT_ROWB + c * 16);
        cp16(aKh + d, g_qh + base + 128);
        cp16(aKl + d, g_ql + base + 128);
        cp16(aVh + d, g_qh + base + 256);
        cp16(aVl + d, g_ql + base + 256);
    }
    CP_COMMIT();
    CP_WAIT(0);
    __syncthreads();

    const float scale = 0.17677669529663687f;
    int fr = lane >> 2, fc = (lane & 3) * 2;
    uint32_t kb_row = (uint32_t)((lane & 7) + ((lane >> 4) << 3));
    uint32_t kb_off = kb_row * AT_ROWB + (((lane >> 3) & 1) << 4);
    uint32_t vt_off = (uint32_t)((lane & 15) * AT_ROWB + ((lane >> 4) << 4));

    for (int mt = wid; mt < tiles; mt += 8) {
        uint32_t qh[2][4], ql[2][4];
        {
            int r1 = start + (mt << 4) + fr, r2 = r1 + 8;
            if (r1 >= NT) r1 = NT - 1;
            if (r2 >= NT) r2 = NT - 1;
            const bf16* q1h = g_qh + (size_t)r1 * 384 + h * 32;
            const bf16* q2h = g_qh + (size_t)r2 * 384 + h * 32;
            const bf16* q1l = g_ql + (size_t)r1 * 384 + h * 32;
            const bf16* q2l = g_ql + (size_t)r2 * 384 + h * 32;
#pragma unroll
            for (int ks = 0; ks < 2; ks++) {
                int d0 = ks * 16 + fc, d8 = d0 + 8;
                qh[ks][0] = *(const uint32_t*)(q1h + d0);
                qh[ks][1] = *(const uint32_t*)(q2h + d0);
                qh[ks][2] = *(const uint32_t*)(q1h + d8);
                qh[ks][3] = *(const uint32_t*)(q2h + d8);
                ql[ks][0] = *(const uint32_t*)(q1l + d0);
                ql[ks][1] = *(const uint32_t*)(q2l + d0);
                ql[ks][2] = *(const uint32_t*)(q1l + d8);
                ql[ks][3] = *(const uint32_t*)(q2l + d8);
            }
        }

        float o[4][4];
#pragma unroll
        for (int i = 0; i < 4; i++)
#pragma unroll
            for (int q = 0; q < 4; q++) o[i][q] = 0.f;
        float m_r = -1e30f, m_r8 = -1e30f;
        float l_r = 0.f, l_r8 = 0.f;

        for (int kt = 0; kt < tiles; kt++) {
            float sacc[2][4];
#pragma unroll
            for (int i = 0; i < 2; i++)
#pragma unroll
                for (int q = 0; q < 4; q++) sacc[i][q] = 0.f;
            {
                uint32_t bhf[2][2][2], blf[2][2][2];
#pragma unroll
                for (int ks = 0; ks < 2; ks++) {
                    uint32_t ad = (uint32_t)(kt * 16 * AT_ROWB) + kb_off + ks * 32;
                    uint32_t t4[4];
                    ldm_x4(t4, aKh + ad);
                    bhf[ks][0][0] = t4[0]; bhf[ks][0][1] = t4[1];
                    bhf[ks][1][0] = t4[2]; bhf[ks][1][1] = t4[3];
                    ldm_x4(t4, aKl + ad);
                    blf[ks][0][0] = t4[0]; blf[ks][0][1] = t4[1];
                    blf[ks][1][0] = t4[2]; blf[ks][1][1] = t4[3];
                }
#pragma unroll
                for (int ks = 0; ks < 2; ks++) {
#pragma unroll
                    for (int n8 = 0; n8 < 2; n8++)
                        mma_bf16(sacc[n8], qh[ks], bhf[ks][n8][0], bhf[ks][n8][1]);
#pragma unroll
                    for (int n8 = 0; n8 < 2; n8++)
                        mma_bf16(sacc[n8], qh[ks], blf[ks][n8][0], blf[ks][n8][1]);
#pragma unroll
                    for (int n8 = 0; n8 < 2; n8++)
                        mma_bf16(sacc[n8], ql[ks], bhf[ks][n8][0], bhf[ks][n8][1]);
                }
            }
            float sv[2][4];
#pragma unroll
            for (int n8 = 0; n8 < 2; n8++)
#pragma unroll
                for (int q = 0; q < 4; q++) {
                    int col = kt * 16 + n8 * 8 + fc + (q & 1);
                    sv[n8][q] = (col < cnt) ? sacc[n8][q] * scale : -1e30f;
                }
            float tm_r  = fmaxf(fmaxf(sv[0][0], sv[0][1]), fmaxf(sv[1][0], sv[1][1]));
            float tm_r8 = fmaxf(fmaxf(sv[0][2], sv[0][3]), fmaxf(sv[1][2], sv[1][3]));
#pragma unroll
            for (int oX = 1; oX <= 2; oX <<= 1) {
                tm_r  = fmaxf(tm_r,  __shfl_xor_sync(0xffffffffu, tm_r,  oX));
                tm_r8 = fmaxf(tm_r8, __shfl_xor_sync(0xffffffffu, tm_r8, oX));
            }
            float Mn_r = fmaxf(m_r, tm_r), Mn_r8 = fmaxf(m_r8, tm_r8);
            float cr = __expf(m_r - Mn_r), cr8 = __expf(m_r8 - Mn_r8);
            m_r = Mn_r; m_r8 = Mn_r8;
            float p[2][4];
#pragma unroll
            for (int n8 = 0; n8 < 2; n8++) {
                p[n8][0] = __expf(sv[n8][0] - Mn_r);
                p[n8][1] = __expf(sv[n8][1] - Mn_r);
                p[n8][2] = __expf(sv[n8][2] - Mn_r8);
                p[n8][3] = __expf(sv[n8][3] - Mn_r8);
            }
            l_r  = l_r  * cr  + p[0][0] + p[0][1] + p[1][0] + p[1][1];
            l_r8 = l_r8 * cr8 + p[0][2] + p[0][3] + p[1][2] + p[1][3];
#pragma unroll
            for (int nn = 0; nn < 4; nn++) {
                o[nn][0] *= cr;  o[nn][1] *= cr;
                o[nn][2] *= cr8; o[nn][3] *= cr8;
            }
            uint32_t pa[4], pl[4];
            {
                bf16 h0, l0, h1, l1;
                split_bf16(p[0][0], h0, l0); split_bf16(p[0][1], h1, l1);
                pa[0] = pack2(h0, h1); pl[0] = pack2(l0, l1);
                split_bf16(p[0][2], h0, l0); split_bf16(p[0][3], h1, l1);
                pa[1] = pack2(h0, h1); pl[1] = pack2(l0, l1);
                split_bf16(p[1][0], h0, l0); split_bf16(p[1][1], h1, l1);
                pa[2] = pack2(h0, h1); pl[2] = pack2(l0, l1);
                split_bf16(p[1][2], h0, l0); split_bf16(p[1][3], h1, l1);
                pa[3] = pack2(h0, h1); pl[3] = pack2(l0, l1);
            }
            uint32_t vhf[4][2], vlf[4][2];
#pragma unroll
            for (int cc = 0; cc < 2; cc++) {
                uint32_t ad = (uint32_t)(kt * 16 * AT_ROWB) + vt_off + cc * 32;
                uint32_t t4[4];
                ldm_x4_t(t4, aVh + ad);
                vhf[cc * 2][0] = t4[0]; vhf[cc * 2][1] = t4[1];
                vhf[cc * 2 + 1][0] = t4[2]; vhf[cc * 2 + 1][1] = t4[3];
                ldm_x4_t(t4, aVl + ad);
                vlf[cc * 2][0] = t4[0]; vlf[cc * 2][1] = t4[1];
                vlf[cc * 2 + 1][0] = t4[2]; vlf[cc * 2 + 1][1] = t4[3];
            }
#pragma unroll
            for (int nn = 0; nn < 4; nn++)
                mma_bf16(o[nn], pa, vhf[nn][0], vhf[nn][1]);
#pragma unroll
            for (int nn = 0; nn < 4; nn++)
                mma_bf16(o[nn], pa, vlf[nn][0], vlf[nn][1]);
#pragma unroll
            for (int nn = 0; nn < 4; nn++)
                mma_bf16(o[nn], pl, vhf[nn][0], vhf[nn][1]);
        }

#pragma unroll
        for (int oX = 1; oX <= 2; oX <<= 1) {
            l_r  += __shfl_xor_sync(0xffffffffu, l_r,  oX);
            l_r8 += __shfl_xor_sync(0xffffffffu, l_r8, oX);
        }
        float i1 = 1.f / l_r, i2 = 1.f / l_r8;
        int lr1 = (mt << 4) + fr, lr2 = lr1 + 8;
#pragma unroll
        for (int nn = 0; nn < 4; nn++) {
            int col = h * 32 + nn * 8 + fc;
            if (lr1 < cnt) {
                float v0 = o[nn][0] * i1, v1 = o[nn][1] * i1;
                bf16 h0, l0, h1, l1;
                split_bf16(v0, h0, l0); split_bf16(v1, h1, l1);
                size_t off = (size_t)(start + lr1) * DD + col;
                *(uint32_t*)(g_ah + off) = pack2(h0, h1);
                *(uint32_t*)(g_al + off) = pack2(l0, l1);
            }
            if (lr2 < cnt) {
                float v0 = o[nn][2] * i2, v1 = o[nn][3] * i2;
                bf16 h0, l0, h1, l1;
                split_bf16(v0, h0, l0); split_bf16(v1, h1, l1);
                size_t off = (size_t)(start + lr2) * DD + col;
                *(uint32_t*)(g_ah + off) = pack2(h0, h1);
                *(uint32_t*)(g_al + off) = pack2(l0, l1);
            }
        }
    }
}

// ---------------- final projection: warp per row ----------------
__global__ __launch_bounds__(256)
void out_kernel(const float* __restrict__ w_out, const float* __restrict__ b_out,
                float* __restrict__ out) {
    int w = threadIdx.x >> 5, lane = threadIdx.x & 31;
    int row = blockIdx.x * 8 + w;
    size_t base = (size_t)row * DD + lane * 4;
    uint2 hx = *(const uint2*)(g_yh + base);
    uint2 lx = *(const uint2*)(g_yl + base);
    float x[4];
#pragma unroll
    for (int j = 0; j < 4; j++) {
        bf16 hb = ((bf16*)&hx)[j], lb = ((bf16*)&lx)[j];
        x[j] = __bfloat162float(hb) + __bfloat162float(lb);
    }
    float p0 = 0.f, p1 = 0.f, p2 = 0.f, p3 = 0.f;
#pragma unroll
    for (int j = 0; j < 4; j++) {
        int t = lane * 4 + j;
        float4 wv = *(const float4*)(w_out + t * 4);
        p0 += x[j] * wv.x; p1 += x[j] * wv.y;
        p2 += x[j] * wv.z; p3 += x[j] * wv.w;
    }
#pragma unroll
    for (int o = 16; o; o >>= 1) {
        p0 += __shfl_xor_sync(0xffffffffu, p0, o);
        p1 += __shfl_xor_sync(0xffffffffu, p1, o);
        p2 += __shfl_xor_sync(0xffffffffu, p2, o);
        p3 += __shfl_xor_sync(0xffffffffu, p3, o);
    }
    if (lane == 0) {
        float4 ov;
        ov.x = p0 + b_out[0];
        ov.y = p1 + b_out[1];
        ov.z = p2 + b_out[2];
        float v3 = p3 + b_out[3];
        ov.w = 1.f / (1.f + __expf(-v3));
        *(float4*)(out + (size_t)row * 4) = ov;
    }
}

// ---------------- launcher ----------------
extern "C" void kernel_launch(void* const* d_in, const int* in_sizes, int n_in,
                              void* d_out, int out_size) {
    const float* inputs_scalar = (const float*)d_in[0];
    const float* inputs_v      = (const float*)d_in[1];
    const int*   batch_idx     = (const int*)  d_in[2];
    const float* bn_gamma      = (const float*)d_in[3];
    const float* bn_beta       = (const float*)d_in[4];
    const float* w_in          = (const float*)d_in[5];
    const float* b_in          = (const float*)d_in[6];
    const float* ln1_g         = (const float*)d_in[7];
    const float* ln1_b         = (const float*)d_in[8];
    const float* w_qkv         = (const float*)d_in[9];
    const float* b_qkv         = (const float*)d_in[10];
    const float* w_o           = (const float*)d_in[11];
    const float* b_o           = (const float*)d_in[12];
    const float* ln2_g         = (const float*)d_in[13];
    const float* ln2_b         = (const float*)d_in[14];
    const float* w_m1          = (const float*)d_in[15];
    const float* b_m1          = (const float*)d_in[16];
    const float* w_m2          = (const float*)d_in[17];
    const float* b_m2          = (const float*)d_in[18];
    const float* lnf_g         = (const float*)d_in[19];
    const float* lnf_b         = (const float*)d_in[20];
    const float* w_out         = (const float*)d_in[21];
    const float* b_out         = (const float*)d_in[22];
    float* out = (float*)d_out;

    (void)in_sizes; (void)n_in; (void)out_size;

    cudaFuncSetAttribute(attn_flash, cudaFuncAttributeMaxDynamicSharedMemorySize, AT_SMEM);
    cudaFuncSetAttribute(gemm_mma<1>, cudaFuncAttributeMaxDynamicSharedMemorySize, GEMM_SMEM);
    cudaFuncSetAttribute(gemm_mma<2>, cudaFuncAttributeMaxDynamicSharedMemorySize, GEMM_SMEM);
    cudaFuncSetAttribute(gemm_mma<3>, cudaFuncAttributeMaxDynamicSharedMemorySize, GEMM_SMEM);
    cudaFuncSetAttribute(gemm_mma<4>, cudaFuncAttributeMaxDynamicSharedMemorySize, GEMM_SMEM);

    float* px;
    bf16 *qh, *ql, *yh, *yl, *ah, *al, *mh, *ml;
    cudaGetSymbolAddress((void**)&px, g_x);
    cudaGetSymbolAddress((void**)&qh, g_qh);
    cudaGetSymbolAddress((void**)&ql, g_ql);
    cudaGetSymbolAddress((void**)&yh, g_yh);
    cudaGetSymbolAddress((void**)&yl, g_yl);
    cudaGetSymbolAddress((void**)&ah, g_ah);
    cudaGetSymbolAddress((void**)&al, g_al);
    cudaGetSymbolAddress((void**)&mh, g_mh);
    cudaGetSymbolAddress((void**)&ml, g_ml);
    bf16 *wqh, *wql, *woh, *wol, *w1h, *w1l, *w2h, *w2l;
    cudaGetSymbolAddress((void**)&wqh, g_wq_hi);
    cudaGetSymbolAddress((void**)&wql, g_wq_lo);
    cudaGetSymbolAddress((void**)&woh, g_wo_hi);
    cudaGetSymbolAddress((void**)&wol, g_wo_lo);
    cudaGetSymbolAddress((void**)&w1h, g_wm1_hi);
    cudaGetSymbolAddress((void**)&w1l, g_wm1_lo);
    cudaGetSymbolAddress((void**)&w2h, g_wm2_hi);
    cudaGetSymbolAddress((void**)&w2l, g_wm2_lo);

    int wtotal = NBLK * (WQ_E + WO_E + W1_E + W2_E);
    wprep_kernel<<<(wtotal + 255) / 256, 256>>>(w_qkv, w_o, w_m1, w_m2);

    bnseg_kernel<<<17, 256>>>(inputs_scalar, inputs_v, batch_idx);
    embed_ln_kernel<<<NT / 8, 256>>>(inputs_scalar, inputs_v, bn_gamma, bn_beta,
                                     w_in, b_in, ln1_g, ln1_b);

    for (int i = 0; i < NBLK; i++) {
        gemm_mma<3><<<dim3(3, NT / 64), 256, GEMM_SMEM>>>(
            yh, yl, wqh + (size_t)i * WQ_E, wql + (size_t)i * WQ_E,
            b_qkv + i * 3 * DD, nullptr, nullptr, qh, ql, 128, 384, nullptr, nullptr);
        attn_flash<<<dim3(GN, HN), 256, AT_SMEM>>>();
        gemm_mma<4><<<dim3(1, NT / 64), 256, GEMM_SMEM>>>(
            ah, al, woh + (size_t)i * WO_E, wol + (size_t)i * WO_E,
            b_o + i * DD, px, px, yh, yl, 128, 128,
            ln2_g + i * DD, ln2_b + i * DD);
        gemm_mma<2><<<dim3(4, NT / 64), 256, GEMM_SMEM>>>(
            yh, yl, w1h + (size_t)i * W1_E, w1l + (size_t)i * W1_E,
            b_m1 + i * 4 * DD, nullptr, nullptr, mh, ml, 128, 512, nullptr, nullptr);
        const float* ng = (i + 1 < NBLK) ? (ln1_g + (i + 1) * DD) : lnf_g;
        const float* nb = (i + 1 < NBLK) ? (ln1_b + (i + 1) * DD) : lnf_b;
        gemm_mma<4><<<dim3(1, NT / 64), 256, GEMM_SMEM>>>(
            mh, ml, w2h + (size_t)i * W2_E, w2l + (size_t)i * W2_E,
            b_m2 + i * DD, px, px, yh, yl, 512, 128, ng, nb);
    }

    out_kernel<<<NT / 8, 256>>>(w_out, b_out, out);
}

// round 16
// speedup vs baseline: 1.2030x; 1.2030x over previous
#include <cuda_runtime.h>
#include <cuda_fp16.h>
#include <cstdint>
#include <math.h>

#define NT   16384
#define GN   128
#define DD   128
#define HN   4
#define DHD  32
#define NBLK 10
#define MAXL 256
#define EPSV 1e-5f

typedef __half f16;

// ---------------- scratch ----------------
__device__ float g_x  [NT * DD];          // residual (fp32)
__device__ f16   g_qh [NT * 3 * DD];      // qkv hi/lo (fp16 pair: attention needs accuracy)
__device__ f16   g_ql [NT * 3 * DD];
__device__ f16   g_y  [NT * DD];          // LN out (single fp16)
__device__ f16   g_a  [NT * DD];          // attention out (single fp16)
__device__ f16   g_m  [NT * 4 * DD];      // MLP hidden (single fp16)
__device__ float g_bn_mean[16];
__device__ float g_bn_rstd[16];
__device__ int   g_seg[GN + 1];

// fp16 hi/lo weights, transposed to [N][K]
__device__ f16 g_wq_hi [NBLK * 384 * 128];
__device__ f16 g_wq_lo [NBLK * 384 * 128];
__device__ f16 g_wo_hi [NBLK * 128 * 128];
__device__ f16 g_wo_lo [NBLK * 128 * 128];
__device__ f16 g_wm1_hi[NBLK * 512 * 128];
__device__ f16 g_wm1_lo[NBLK * 512 * 128];
__device__ f16 g_wm2_hi[NBLK * 128 * 512];
__device__ f16 g_wm2_lo[NBLK * 128 * 512];

// ---------------- asm helpers ----------------
__device__ __forceinline__ uint32_t smem_u32(const void* p) {
    uint32_t a;
    asm("{ .reg .u64 t; cvta.to.shared.u64 t, %1; cvt.u32.u64 %0, t; }" : "=r"(a) : "l"(p));
    return a;
}
__device__ __forceinline__ void cp16(uint32_t dst, const void* src) {
    asm volatile("cp.async.cg.shared.global [%0], [%1], 16;" :: "r"(dst), "l"(src));
}
#define CP_COMMIT() asm volatile("cp.async.commit_group;" ::: "memory")
#define CP_WAIT(n)  asm volatile("cp.async.wait_group %0;" :: "n"(n) : "memory")

__device__ __forceinline__ void ldm_x4(uint32_t r[4], uint32_t a) {
    asm volatile("ldmatrix.sync.aligned.m8n8.x4.shared.b16 {%0,%1,%2,%3}, [%4];"
                 : "=r"(r[0]), "=r"(r[1]), "=r"(r[2]), "=r"(r[3]) : "r"(a));
}
__device__ __forceinline__ void ldm_x4_t(uint32_t r[4], uint32_t a) {
    asm volatile("ldmatrix.sync.aligned.m8n8.x4.trans.shared.b16 {%0,%1,%2,%3}, [%4];"
                 : "=r"(r[0]), "=r"(r[1]), "=r"(r[2]), "=r"(r[3]) : "r"(a));
}
__device__ __forceinline__ void mma_f16(float c[4], const uint32_t a[4],
                                        uint32_t b0, uint32_t b1) {
    asm volatile(
        "mma.sync.aligned.m16n8k16.row.col.f32.f16.f16.f32 "
        "{%0,%1,%2,%3}, {%4,%5,%6,%7}, {%8,%9}, {%0,%1,%2,%3};"
        : "+f"(c[0]), "+f"(c[1]), "+f"(c[2]), "+f"(c[3])
        : "r"(a[0]), "r"(a[1]), "r"(a[2]), "r"(a[3]), "r"(b0), "r"(b1));
}

__device__ __forceinline__ void split_f16(float v, f16& hi, f16& lo) {
    hi = __float2half(v);
    lo = __float2half(v - __half2float(hi));
}
__device__ __forceinline__ uint32_t pack2h(f16 a, f16 b) {
    __half2 t = {a, b};
    return *(uint32_t*)&t;
}
__device__ __forceinline__ float fast_gelu(float u) {
    float z = 0.7978845608028654f * (u + 0.044715f * u * u * u);
    float t = 1.f - 2.f / (__expf(2.f * z) + 1.f);
    return 0.5f * u * (1.f + t);
}

// ---------------- merged BN stats + segment offsets ----------------
__global__ void bnseg_kernel(const float* __restrict__ s, const float* __restrict__ v,
                             const int* __restrict__ bidx) {
    if (blockIdx.x < 16) {
        int f = blockIdx.x, t = threadIdx.x;
        float sum = 0.f, sq = 0.f;
        for (int i = t; i < NT; i += 256) {
            float x = (f < 13) ? s[i * 13 + f] : v[i * 3 + (f - 13)];
            sum += x; sq += x * x;
        }
        __shared__ float rs[256], rq[256];
        rs[t] = sum; rq[t] = sq;
        __syncthreads();
        for (int st = 128; st > 0; st >>= 1) {
            if (t < st) { rs[t] += rs[t + st]; rq[t] += rq[t + st]; }
            __syncthreads();
        }
        if (t == 0) {
            float m = rs[0] * (1.f / NT);
            float var = rq[0] * (1.f / NT) - m * m;
            g_bn_mean[f] = m;
            g_bn_rstd[f] = rsqrtf(var + EPSV);
        }
    } else {
        int g = threadIdx.x;
        if (g > GN) return;
        int lo = 0, hi = NT;
        while (lo < hi) {
            int mid = (lo + hi) >> 1;
            if (bidx[mid] < g) lo = mid + 1; else hi = mid;
        }
        g_seg[g] = lo;
    }
}

// ---------------- BN + embed + LN1[0], warp per row ----------------
__global__ __launch_bounds__(256)
void embed_ln_kernel(const float* __restrict__ s, const float* __restrict__ v,
                     const float* __restrict__ gamma, const float* __restrict__ beta,
                     const float* __restrict__ w_in, const float* __restrict__ b_in,
                     const float* __restrict__ gam, const float* __restrict__ bet) {
    int w = threadIdx.x >> 5, lane = threadIdx.x & 31;
    int row = blockIdx.x * 8 + w;
    float4 bi = *(const float4*)(b_in + lane * 4);
    float4 gv = *(const float4*)(gam + lane * 4);
    float4 bv = *(const float4*)(bet + lane * 4);
    float xr = 0.f, gmr = 0.f, btr = 0.f, mnr = 0.f, rsr = 0.f;
    if (lane < 16) {
        xr = (lane < 13) ? s[row * 13 + lane] : v[row * 3 + (lane - 13)];
        gmr = gamma[lane]; btr = beta[lane];
        mnr = g_bn_mean[lane]; rsr = g_bn_rstd[lane];
    }
    float xn = (xr - mnr) * rsr * gmr + btr;
    float acc[4] = {bi.x, bi.y, bi.z, bi.w};
#pragma unroll
    for (int k = 0; k < 16; k++) {
        float xk = __shfl_sync(0xffffffffu, xn, k);
        float4 wv = *(const float4*)(w_in + k * DD + lane * 4);
        acc[0] += xk * wv.x; acc[1] += xk * wv.y;
        acc[2] += xk * wv.z; acc[3] += xk * wv.w;
    }
    *(float4*)(g_x + (size_t)row * DD + lane * 4) = *(float4*)acc;
    float ssum = acc[0] + acc[1] + acc[2] + acc[3];
    float sqs = acc[0]*acc[0] + acc[1]*acc[1] + acc[2]*acc[2] + acc[3]*acc[3];
#pragma unroll
    for (int o = 16; o; o >>= 1) {
        ssum += __shfl_xor_sync(0xffffffffu, ssum, o);
        sqs  += __shfl_xor_sync(0xffffffffu, sqs,  o);
    }
    float m = ssum * (1.f / DD);
    float var = sqs * (1.f / DD) - m * m;
    float r = rsqrtf(var + EPSV);
    f16 h[4];
    h[0] = __float2half((acc[0] - m) * r * gv.x + bv.x);
    h[1] = __float2half((acc[1] - m) * r * gv.y + bv.y);
    h[2] = __float2half((acc[2] - m) * r * gv.z + bv.z);
    h[3] = __float2half((acc[3] - m) * r * gv.w + bv.w);
    *(uint2*)(g_y + (size_t)row * DD + lane * 4) = *(uint2*)h;
}

// ---------------- merged weight prep ----------------
#define WQ_E (384 * 128)
#define WO_E (128 * 128)
#define W1_E (512 * 128)
#define W2_E (128 * 512)
__global__ void wprep_kernel(const float* __restrict__ wq, const float* __restrict__ wo,
                             const float* __restrict__ w1, const float* __restrict__ w2) {
    int idx = blockIdx.x * 256 + threadIdx.x;
    const float* w; f16 *whi, *wlo; int K, N, li;
    if (idx < NBLK * WQ_E) {
        w = wq; whi = g_wq_hi; wlo = g_wq_lo; K = 128; N = 384; li = idx;
    } else if (idx < NBLK * (WQ_E + WO_E)) {
        w = wo; whi = g_wo_hi; wlo = g_wo_lo; K = 128; N = 128; li = idx - NBLK * WQ_E;
    } else if (idx < NBLK * (WQ_E + WO_E + W1_E)) {
        w = w1; whi = g_wm1_hi; wlo = g_wm1_lo; K = 128; N = 512; li = idx - NBLK * (WQ_E + WO_E);
    } else if (idx < NBLK * (WQ_E + WO_E + W1_E + W2_E)) {
        w = w2; whi = g_wm2_hi; wlo = g_wm2_lo; K = 512; N = 128; li = idx - NBLK * (WQ_E + WO_E + W1_E);
    } else return;
    int k = li % K;
    int n = (li / K) % N;
    int b = li / (K * N);
    float x = w[(size_t)b * K * N + (size_t)k * N + n];
    f16 hi, lo;
    split_f16(x, hi, lo);
    whi[li] = hi;
    wlo[li] = lo;
}

// ---------------- chunk-pipelined GEMM: fp16 split-weights, 2-MMA ----------------
// C = A(f16) @ (Whi + Wlo)^T. BM=64, BN=128, 64-K chunks double-buffered.
// 256 threads, 8 warps 2(m) x 4(n), warp tile 32x32.
// Buffer (RS=144 conflict-free): A 64 rows | B hi 128 | B lo 128 -> 46080 B.
// FUSE: 2 bias+gelu->f16, 3 bias->hi/lo f16 pair, 4 bias+res->fp32 + LN -> f16
#define RS      144
#define CB_H    9216
#define CB_L    27648
#define CBUF    46080
#define GEMM_SMEM (2 * CBUF)   // 92160

template <int FUSE>
__global__ __launch_bounds__(256, 2)
void gemm_mma(const f16* __restrict__ A,
              const f16* __restrict__ Bhi, const f16* __restrict__ Blo,
              const float* __restrict__ bias, const float* __restrict__ R,
              float* __restrict__ C, f16* __restrict__ Chi, f16* __restrict__ Clo,
              int K, int Nc,
              const float* __restrict__ lngam, const float* __restrict__ lnbet) {
    extern __shared__ char smem[];
    uint32_t sb = smem_u32(smem);
    int tid = threadIdx.x, lane = tid & 31, wid = tid >> 5;
    int wm = wid & 1, wn = wid >> 1;
    int m0 = blockIdx.y * 64, n0 = blockIdx.x * 128;

    int seg = tid & 7;
    int rowb = tid >> 3;                      // 0..31
    int scol = seg * 16;

    float acc[2][4][4];
#pragma unroll
    for (int i = 0; i < 2; i++)
#pragma unroll
        for (int j = 0; j < 4; j++)
#pragma unroll
            for (int q = 0; q < 4; q++) acc[i][j][q] = 0.f;

    uint32_t a_off = (uint32_t)((wm * 32 + (lane & 15)) * RS + ((lane >> 4) << 4));
    uint32_t b_lane = (uint32_t)((lane & 7) + ((lane >> 4) << 3));
    uint32_t b_half = ((lane >> 3) & 1) << 4;
    uint32_t b_off = (uint32_t)((wn * 32 + b_lane) * RS + b_half);

    int nh = K >> 6;

    // 320 rows x 8 segs; 256 thr -> 10 passes of 32 rows
    auto stage = [&](int h, int b) {
        uint32_t base = sb + (uint32_t)b * CBUF;
        int kc = h << 6;
#pragma unroll
        for (int i = 0; i < 10; i++) {
            int rr = rowb + i * 32;            // 0..319
            uint32_t dst; const f16* src;
            if (rr < 64) {
                dst = base + rr * RS;
                src = A + (size_t)(m0 + rr) * K + kc;
            } else if (rr < 192) {
                int r = rr - 64;
                dst = base + CB_H + r * RS;
                src = Bhi + (size_t)(n0 + r) * K + kc;
            } else {
                int r = rr - 192;
                dst = base + CB_L + r * RS;
                src = Blo + (size_t)(n0 + r) * K + kc;
            }
            cp16(dst + scol, (const char*)src + scol);
        }
    };

    stage(0, 0);
    CP_COMMIT();

    for (int h = 0; h < nh; h++) {
        __syncthreads();               // WAR: all warps done with buffer (h+1)&1
        if (h + 1 < nh) stage(h + 1, (h + 1) & 1);
        CP_COMMIT();
        CP_WAIT(1);                    // chunk h landed
        __syncthreads();

        uint32_t base = sb + (uint32_t)(h & 1) * CBUF;
        uint32_t aB = base + a_off;
        uint32_t bB = base + CB_H + b_off;

#pragma unroll
        for (int s = 0; s < 4; s++) {
            uint32_t koff = (uint32_t)(s * 32);
            uint32_t ah[2][4];
#pragma unroll
            for (int mt = 0; mt < 2; mt++)
                ldm_x4(ah[mt], aB + mt * 16 * RS + koff);
            uint32_t bh[4][2], bl[4][2];
#pragma unroll
            for (int g4 = 0; g4 < 2; g4++) {
                uint32_t addr = bB + g4 * 16 * RS + koff;
                uint32_t t4[4];
                ldm_x4(t4, addr);
                bh[g4 * 2][0] = t4[0]; bh[g4 * 2][1] = t4[1];
                bh[g4 * 2 + 1][0] = t4[2]; bh[g4 * 2 + 1][1] = t4[3];
                ldm_x4(t4, addr + (CB_L - CB_H));
                bl[g4 * 2][0] = t4[0]; bl[g4 * 2][1] = t4[1];
                bl[g4 * 2 + 1][0] = t4[2]; bl[g4 * 2 + 1][1] = t4[3];
            }
            // per-acc order: a*bhi then a*blo (deterministic)
#pragma unroll
            for (int mt = 0; mt < 2; mt++)
#pragma unroll
                for (int nt = 0; nt < 4; nt++)
                    mma_f16(acc[mt][nt], ah[mt], bh[nt][0], bh[nt][1]);
#pragma unroll
            for (int mt = 0; mt < 2; mt++)
#pragma unroll
                for (int nt = 0; nt < 4; nt++)
                    mma_f16(acc[mt][nt], ah[mt], bl[nt][0], bl[nt][1]);
        }
    }

    float* xbuf = (float*)smem;   // FUSE=4: [64][132] fp32 residual tile
    if (FUSE == 4) __syncthreads();

    int lane4 = lane >> 2, lanem = (lane & 3) * 2;
#pragma unroll
    for (int mt = 0; mt < 2; mt++) {
#pragma unroll
        for (int nt = 0; nt < 4; nt++) {
            int col = n0 + wn * 32 + nt * 8 + lanem;
            int r0 = m0 + wm * 32 + mt * 16 + lane4;
            float2 bb = *(const float2*)(bias + col);
#pragma unroll
            for (int half = 0; half < 2; half++) {
                int r = r0 + half * 8;
                float v0 = acc[mt][nt][half * 2 + 0] + bb.x;
                float v1 = acc[mt][nt][half * 2 + 1] + bb.y;
                size_t o = (size_t)r * Nc + col;
                if (FUSE == 4) {
                    float2 rr = *(const float2*)(R + o);
                    v0 += rr.x; v1 += rr.y;
                    float2 ov = {v0, v1};
                    *(float2*)(C + o) = ov;
                    xbuf[(r - m0) * 132 + col] = v0;
                    xbuf[(r - m0) * 132 + col + 1] = v1;
                } else if (FUSE == 2) {
                    v0 = fast_gelu(v0);
                    v1 = fast_gelu(v1);
                    *(uint32_t*)(Chi + o) = pack2h(__float2half(v0), __float2half(v1));
                } else {  // FUSE == 3: hi/lo pair
                    f16 h0, l0, h1, l1;
                    split_f16(v0, h0, l0);
                    split_f16(v1, h1, l1);
                    *(uint32_t*)(Chi + o) = pack2h(h0, h1);
                    *(uint32_t*)(Clo + o) = pack2h(l0, l1);
                }
            }
        }
    }

    if (FUSE == 4) {
        __syncthreads();
#pragma unroll
        for (int rr = wid; rr < 64; rr += 8) {
            float4 xv = *(float4*)(xbuf + rr * 132 + lane * 4);
            float s = xv.x + xv.y + xv.z + xv.w;
            float sq = xv.x*xv.x + xv.y*xv.y + xv.z*xv.z + xv.w*xv.w;
#pragma unroll
            for (int o = 16; o; o >>= 1) {
                s  += __shfl_xor_sync(0xffffffffu, s,  o);
                sq += __shfl_xor_sync(0xffffffffu, sq, o);
            }
            float m = s * (1.f / DD);
            float var = sq * (1.f / DD) - m * m;
            float rcp = rsqrtf(var + EPSV);
            float4 gv = *(const float4*)(lngam + lane * 4);
            float4 bv = *(const float4*)(lnbet + lane * 4);
            f16 h[4];
            h[0] = __float2half((xv.x - m) * rcp * gv.x + bv.x);
            h[1] = __float2half((xv.y - m) * rcp * gv.y + bv.y);
            h[2] = __float2half((xv.z - m) * rcp * gv.z + bv.z);
            h[3] = __float2half((xv.w - m) * rcp * gv.w + bv.w);
            size_t off = (size_t)(m0 + rr) * DD + lane * 4;
            *(uint2*)(Chi + off) = *(uint2*)h;
        }
    }
}

// ---------------- flash segment attention (fp16 hi/lo, single-f16 output) ----------------
#define AT_ROWB 80
#define AT_ARR  (MAXL * AT_ROWB)
#define AT_SMEM (4 * AT_ARR)

__global__ __launch_bounds__(256)
void attn_flash() {
    extern __shared__ char sm[];
    f16* sKh = (f16*)sm;
    f16* sKl = (f16*)(sm + AT_ARR);
    f16* sVh = (f16*)(sm + 2 * AT_ARR);
    f16* sVl = (f16*)(sm + 3 * AT_ARR);

    int g = blockIdx.x, h = blockIdx.y;
    int start = g_seg[g];
    int cnt = g_seg[g + 1] - start;
    if (cnt <= 0) return;
    if (cnt > MAXL) cnt = MAXL;
    int tid = threadIdx.x, lane = tid & 31, wid = tid >> 5;
    int tiles = (cnt + 15) >> 4;
    int ncols = tiles << 4;

    uint32_t aKh = smem_u32(sKh), aKl = smem_u32(sKl);
    uint32_t aVh = smem_u32(sVh), aVl = smem_u32(sVl);

    {
        uint4 z = {0, 0, 0, 0};
        int npad = (ncols - cnt) * 4;
        for (int idx = tid; idx < npad; idx += 256) {
            int j = cnt + (idx >> 2), c = idx & 3;
            int o = j * AT_ROWB + c * 16;
            *(uint4*)((char*)sKh + o) = z;
            *(uint4*)((char*)sKl + o) = z;
            *(uint4*)((char*)sVh + o) = z;
            *(uint4*)((char*)sVl + o) = z;
        }
    }
    for (int idx = tid; idx < cnt * 4; idx += 256) {
        int j = idx >> 2, c = idx & 3;
        size_t base = (size_t)(start + j) * 384 + h * 32 + c * 8;
        uint32_t d = (uint32_t)(j * AT_ROWB + c * 16);
        cp16(aKh + d, g_qh + base + 128);
        cp16(aKl + d, g_ql + base + 128);
        cp16(aVh + d, g_qh + base + 256);
        cp16(aVl + d, g_ql + base + 256);
    }
    CP_COMMIT();
    CP_WAIT(0);
    __syncthreads();

    const float scale = 0.17677669529663687f;
    int fr = lane >> 2, fc = (lane & 3) * 2;
    uint32_t kb_row = (uint32_t)((lane & 7) + ((lane >> 4) << 3));
    uint32_t kb_off = kb_row * AT_ROWB + (((lane >> 3) & 1) << 4);
    uint32_t vt_off = (uint32_t)((lane & 15) * AT_ROWB + ((lane >> 4) << 4));

    for (int mt = wid; mt < tiles; mt += 8) {
        uint32_t qh[2][4], ql[2][4];
        {
            int r1 = start + (mt << 4) + fr, r2 = r1 + 8;
            if (r1 >= NT) r1 = NT - 1;
            if (r2 >= NT) r2 = NT - 1;
            const f16* q1h = g_qh + (size_t)r1 * 384 + h * 32;
            const f16* q2h = g_qh + (size_t)r2 * 384 + h * 32;
            const f16* q1l = g_ql + (size_t)r1 * 384 + h * 32;
            const f16* q2l = g_ql + (size_t)r2 * 384 + h * 32;
#pragma unroll
            for (int ks = 0; ks < 2; ks++) {
                int d0 = ks * 16 + fc, d8 = d0 + 8;
                qh[ks][0] = *(const uint32_t*)(q1h + d0);
                qh[ks][1] = *(const uint32_t*)(q2h + d0);
                qh[ks][2] = *(const uint32_t*)(q1h + d8);
                qh[ks][3] = *(const uint32_t*)(q2h + d8);
                ql[ks][0] = *(const uint32_t*)(q1l + d0);
                ql[ks][1] = *(const uint32_t*)(q2l + d0);
                ql[ks][2] = *(const uint32_t*)(q1l + d8);
                ql[ks][3] = *(const uint32_t*)(q2l + d8);
            }
        }

        float o[4][4];
#pragma unroll
        for (int i = 0; i < 4; i++)
#pragma unroll
            for (int q = 0; q < 4; q++) o[i][q] = 0.f;
        float m_r = -1e30f, m_r8 = -1e30f;
        float l_r = 0.f, l_r8 = 0.f;

        for (int kt = 0; kt < tiles; kt++) {
            float sacc[2][4];
#pragma unroll
            for (int i = 0; i < 2; i++)
#pragma unroll
                for (int q = 0; q < 4; q++) sacc[i][q] = 0.f;
            {
                uint32_t bhf[2][2][2], blf[2][2][2];
#pragma unroll
                for (int ks = 0; ks < 2; ks++) {
                    uint32_t ad = (uint32_t)(kt * 16 * AT_ROWB) + kb_off + ks * 32;
                    uint32_t t4[4];
                    ldm_x4(t4, aKh + ad);
                    bhf[ks][0][0] = t4[0]; bhf[ks][0][1] = t4[1];
                    bhf[ks][1][0] = t4[2]; bhf[ks][1][1] = t4[3];
                    ldm_x4(t4, aKl + ad);
                    blf[ks][0][0] = t4[0]; blf[ks][0][1] = t4[1];
                    blf[ks][1][0] = t4[2]; blf[ks][1][1] = t4[3];
                }
#pragma unroll
                for (int ks = 0; ks < 2; ks++) {
#pragma unroll
                    for (int n8 = 0; n8 < 2; n8++)
                        mma_f16(sacc[n8], qh[ks], bhf[ks][n8][0], bhf[ks][n8][1]);
#pragma unroll
                    for (int n8 = 0; n8 < 2; n8++)
                        mma_f16(sacc[n8], qh[ks], blf[ks][n8][0], blf[ks][n8][1]);
#pragma unroll
                    for (int n8 = 0; n8 < 2; n8++)
                        mma_f16(sacc[n8], ql[ks], bhf[ks][n8][0], bhf[ks][n8][1]);
                }
            }
            float sv[2][4];
#pragma unroll
            for (int n8 = 0; n8 < 2; n8++)
#pragma unroll
                for (int q = 0; q < 4; q++) {
                    int col = kt * 16 + n8 * 8 + fc + (q & 1);
                    sv[n8][q] = (col < cnt) ? sacc[n8][q] * scale : -1e30f;
                }
            float tm_r  = fmaxf(fmaxf(sv[0][0], sv[0][1]), fmaxf(sv[1][0], sv[1][1]));
            float tm_r8 = fmaxf(fmaxf(sv[0][2], sv[0][3]), fmaxf(sv[1][2], sv[1][3]));
#pragma unroll
            for (int oX = 1; oX <= 2; oX <<= 1) {
                tm_r  = fmaxf(tm_r,  __shfl_xor_sync(0xffffffffu, tm_r,  oX));
                tm_r8 = fmaxf(tm_r8, __shfl_xor_sync(0xffffffffu, tm_r8, oX));
            }
            float Mn_r = fmaxf(m_r, tm_r), Mn_r8 = fmaxf(m_r8, tm_r8);
            float cr = __expf(m_r - Mn_r), cr8 = __expf(m_r8 - Mn_r8);
            m_r = Mn_r; m_r8 = Mn_r8;
            float p[2][4];
#pragma unroll
            for (int n8 = 0; n8 < 2; n8++) {
                p[n8][0] = __expf(sv[n8][0] - Mn_r);
                p[n8][1] = __expf(sv[n8][1] - Mn_r);
                p[n8][2] = __expf(sv[n8][2] - Mn_r8);
                p[n8][3] = __expf(sv[n8][3] - Mn_r8);
            }
            l_r  = l_r  * cr  + p[0][0] + p[0][1] + p[1][0] + p[1][1];
            l_r8 = l_r8 * cr8 + p[0][2] + p[0][3] + p[1][2] + p[1][3];
#pragma unroll
            for (int nn = 0; nn < 4; nn++) {
                o[nn][0] *= cr;  o[nn][1] *= cr;
                o[nn][2] *= cr8; o[nn][3] *= cr8;
            }
            uint32_t pa[4], pl[4];
            {
                f16 h0, l0, h1, l1;
                split_f16(p[0][0], h0, l0); split_f16(p[0][1], h1, l1);
                pa[0] = pack2h(h0, h1); pl[0] = pack2h(l0, l1);
                split_f16(p[0][2], h0, l0); split_f16(p[0][3], h1, l1);
                pa[1] = pack2h(h0, h1); pl[1] = pack2h(l0, l1);
                split_f16(p[1][0], h0, l0); split_f16(p[1][1], h1, l1);
                pa[2] = pack2h(h0, h1); pl[2] = pack2h(l0, l1);
                split_f16(p[1][2], h0, l0); split_f16(p[1][3], h1, l1);
                pa[3] = pack2h(h0, h1); pl[3] = pack2h(l0, l1);
            }
            uint32_t vhf[4][2], vlf[4][2];
#pragma unroll
            for (int cc = 0; cc < 2; cc++) {
                uint32_t ad = (uint32_t)(kt * 16 * AT_ROWB) + vt_off + cc * 32;
                uint32_t t4[4];
                ldm_x4_t(t4, aVh + ad);
                vhf[cc * 2][0] = t4[0]; vhf[cc * 2][1] = t4[1];
                vhf[cc * 2 + 1][0] = t4[2]; vhf[cc * 2 + 1][1] = t4[3];
                ldm_x4_t(t4, aVl + ad);
                vlf[cc * 2][0] = t4[0]; vlf[cc * 2][1] = t4[1];
                vlf[cc * 2 + 1][0] = t4[2]; vlf[cc * 2 + 1][1] = t4[3];
            }
#pragma unroll
            for (int nn = 0; nn < 4; nn++)
                mma_f16(o[nn], pa, vhf[nn][0], vhf[nn][1]);
#pragma unroll
            for (int nn = 0; nn < 4; nn++)
                mma_f16(o[nn], pa, vlf[nn][0], vlf[nn][1]);
#pragma unroll
            for (int nn = 0; nn < 4; nn++)
                mma_f16(o[nn], pl, vhf[nn][0], vhf[nn][1]);
        }

#pragma unroll
        for (int oX = 1; oX <= 2; oX <<= 1) {
            l_r  += __shfl_xor_sync(0xffffffffu, l_r,  oX);
            l_r8 += __shfl_xor_sync(0xffffffffu, l_r8, oX);
        }
        float i1 = 1.f / l_r, i2 = 1.f / l_r8;
        int lr1 = (mt << 4) + fr, lr2 = lr1 + 8;
#pragma unroll
        for (int nn = 0; nn < 4; nn++) {
            int col = h * 32 + nn * 8 + fc;
            if (lr1 < cnt) {
                size_t off = (size_t)(start + lr1) * DD + col;
                *(uint32_t*)(g_a + off) =
                    pack2h(__float2half(o[nn][0] * i1), __float2half(o[nn][1] * i1));
            }
            if (lr2 < cnt) {
                size_t off = (size_t)(start + lr2) * DD + col;
                *(uint32_t*)(g_a + off) =
                    pack2h(__float2half(o[nn][2] * i2), __float2half(o[nn][3] * i2));
            }
        }
    }
}

// ---------------- final projection: warp per row ----------------
__global__ __launch_bounds__(256)
void out_kernel(const float* __restrict__ w_out, const float* __restrict__ b_out,
                float* __restrict__ out) {
    int w = threadIdx.x >> 5, lane = threadIdx.x & 31;
    int row = blockIdx.x * 8 + w;
    size_t base = (size_t)row * DD + lane * 4;
    uint2 hx = *(const uint2*)(g_y + base);
    float x[4];
#pragma unroll
    for (int j = 0; j < 4; j++)
        x[j] = __half2float(((f16*)&hx)[j]);
    float p0 = 0.f, p1 = 0.f, p2 = 0.f, p3 = 0.f;
#pragma unroll
    for (int j = 0; j < 4; j++) {
        int t = lane * 4 + j;
        float4 wv = *(const float4*)(w_out + t * 4);
        p0 += x[j] * wv.x; p1 += x[j] * wv.y;
        p2 += x[j] * wv.z; p3 += x[j] * wv.w;
    }
#pragma unroll
    for (int o = 16; o; o >>= 1) {
        p0 += __shfl_xor_sync(0xffffffffu, p0, o);
        p1 += __shfl_xor_sync(0xffffffffu, p1, o);
        p2 += __shfl_xor_sync(0xffffffffu, p2, o);
        p3 += __shfl_xor_sync(0xffffffffu, p3, o);
    }
    if (lane == 0) {
        float4 ov;
        ov.x = p0 + b_out[0];
        ov.y = p1 + b_out[1];
        ov.z = p2 + b_out[2];
        float v3 = p3 + b_out[3];
        ov.w = 1.f / (1.f + __expf(-v3));
        *(float4*)(out + (size_t)row * 4) = ov;
    }
}

// ---------------- launcher ----------------
extern "C" void kernel_launch(void* const* d_in, const int* in_sizes, int n_in,
                              void* d_out, int out_size) {
    const float* inputs_scalar = (const float*)d_in[0];
    const float* inputs_v      = (const float*)d_in[1];
    const int*   batch_idx     = (const int*)  d_in[2];
    const float* bn_gamma      = (const float*)d_in[3];
    const float* bn_beta       = (const float*)d_in[4];
    const float* w_in          = (const float*)d_in[5];
    const float* b_in          = (const float*)d_in[6];
    const float* ln1_g         = (const float*)d_in[7];
    const float* ln1_b         = (const float*)d_in[8];
    const float* w_qkv         = (const float*)d_in[9];
    const float* b_qkv         = (const float*)d_in[10];
    const float* w_o           = (const float*)d_in[11];
    const float* b_o           = (const float*)d_in[12];
    const float* ln2_g         = (const float*)d_in[13];
    const float* ln2_b         = (const float*)d_in[14];
    const float* w_m1          = (const float*)d_in[15];
    const float* b_m1          = (const float*)d_in[16];
    const float* w_m2          = (const float*)d_in[17];
    const float* b_m2          = (const float*)d_in[18];
    const float* lnf_g         = (const float*)d_in[19];
    const float* lnf_b         = (const float*)d_in[20];
    const float* w_out         = (const float*)d_in[21];
    const float* b_out         = (const float*)d_in[22];
    float* out = (float*)d_out;

    (void)in_sizes; (void)n_in; (void)out_size;

    cudaFuncSetAttribute(attn_flash, cudaFuncAttributeMaxDynamicSharedMemorySize, AT_SMEM);
    cudaFuncSetAttribute(gemm_mma<2>, cudaFuncAttributeMaxDynamicSharedMemorySize, GEMM_SMEM);
    cudaFuncSetAttribute(gemm_mma<3>, cudaFuncAttributeMaxDynamicSharedMemorySize, GEMM_SMEM);
    cudaFuncSetAttribute(gemm_mma<4>, cudaFuncAttributeMaxDynamicSharedMemorySize, GEMM_SMEM);

    float* px;
    f16 *qh, *ql, *py, *pa, *pm;
    cudaGetSymbolAddress((void**)&px, g_x);
    cudaGetSymbolAddress((void**)&qh, g_qh);
    cudaGetSymbolAddress((void**)&ql, g_ql);
    cudaGetSymbolAddress((void**)&py, g_y);
    cudaGetSymbolAddress((void**)&pa, g_a);
    cudaGetSymbolAddress((void**)&pm, g_m);
    f16 *wqh, *wql, *woh, *wol, *w1h, *w1l, *w2h, *w2l;
    cudaGetSymbolAddress((void**)&wqh, g_wq_hi);
    cudaGetSymbolAddress((void**)&wql, g_wq_lo);
    cudaGetSymbolAddress((void**)&woh, g_wo_hi);
    cudaGetSymbolAddress((void**)&wol, g_wo_lo);
    cudaGetSymbolAddress((void**)&w1h, g_wm1_hi);
    cudaGetSymbolAddress((void**)&w1l, g_wm1_lo);
    cudaGetSymbolAddress((void**)&w2h, g_wm2_hi);
    cudaGetSymbolAddress((void**)&w2l, g_wm2_lo);

    int wtotal = NBLK * (WQ_E + WO_E + W1_E + W2_E);
    wprep_kernel<<<(wtotal + 255) / 256, 256>>>(w_qkv, w_o, w_m1, w_m2);

    bnseg_kernel<<<17, 256>>>(inputs_scalar, inputs_v, batch_idx);
    embed_ln_kernel<<<NT / 8, 256>>>(inputs_scalar, inputs_v, bn_gamma, bn_beta,
                                     w_in, b_in, ln1_g, ln1_b);

    for (int i = 0; i < NBLK; i++) {
        gemm_mma<3><<<dim3(3, NT / 64), 256, GEMM_SMEM>>>(
            py, wqh + (size_t)i * WQ_E, wql + (size_t)i * WQ_E,
            b_qkv + i * 3 * DD, nullptr, nullptr, qh, ql, 128, 384, nullptr, nullptr);
        attn_flash<<<dim3(GN, HN), 256, AT_SMEM>>>();
        gemm_mma<4><<<dim3(1, NT / 64), 256, GEMM_SMEM>>>(
            pa, woh + (size_t)i * WO_E, wol + (size_t)i * WO_E,
            b_o + i * DD, px, px, py, nullptr, 128, 128,
            ln2_g + i * DD, ln2_b + i * DD);
        gemm_mma<2><<<dim3(4, NT / 64), 256, GEMM_SMEM>>>(
            py, w1h + (size_t)i * W1_E, w1l + (size_t)i * W1_E,
            b_m1 + i * 4 * DD, nullptr, nullptr, pm, nullptr, 128, 512, nullptr, nullptr);
        const float* ng = (i + 1 < NBLK) ? (ln1_g + (i + 1) * DD) : lnf_g;
        const float* nb = (i + 1 < NBLK) ? (ln1_b + (i + 1) * DD) : lnf_b;
        gemm_mma<4><<<dim3(1, NT / 64), 256, GEMM_SMEM>>>(
            pm, w2h + (size_t)i * W2_E, w2l + (size_t)i * W2_E,
            b_m2 + i * DD, px, px, py, nullptr, 512, 128, ng, nb);
    }

    out_kernel<<<NT / 8, 256>>>(w_out, b_out, out);
}

// round 17
// speedup vs baseline: 1.4795x; 1.2299x over previous
#include <cuda_runtime.h>
#include <cuda_fp16.h>
#include <cstdint>
#include <math.h>

#define NT   16384
#define GN   128
#define DD   128
#define HN   4
#define DHD  32
#define NBLK 10
#define MAXL 256
#define EPSV 1e-5f

typedef __half f16;

// ---------------- scratch ----------------
__device__ float g_x  [NT * DD];          // residual (fp32)
__device__ f16   g_qh [NT * 3 * DD];      // qkv hi/lo (attention needs accuracy)
__device__ f16   g_ql [NT * 3 * DD];
__device__ f16   g_y  [NT * DD];          // LN out (single fp16)
__device__ f16   g_a  [NT * DD];          // attention out (single fp16)
__device__ f16   g_m  [NT * 4 * DD];      // MLP hidden (single fp16)
__device__ float g_bn_mean[16];
__device__ float g_bn_rstd[16];
__device__ int   g_seg[GN + 1];

// single fp16 weights, transposed to [N][K]
__device__ f16 g_wq [NBLK * 384 * 128];
__device__ f16 g_wo [NBLK * 128 * 128];
__device__ f16 g_wm1[NBLK * 512 * 128];
__device__ f16 g_wm2[NBLK * 128 * 512];

// ---------------- asm helpers ----------------
__device__ __forceinline__ uint32_t smem_u32(const void* p) {
    uint32_t a;
    asm("{ .reg .u64 t; cvta.to.shared.u64 t, %1; cvt.u32.u64 %0, t; }" : "=r"(a) : "l"(p));
    return a;
}
__device__ __forceinline__ void cp16(uint32_t dst, const void* src) {
    asm volatile("cp.async.cg.shared.global [%0], [%1], 16;" :: "r"(dst), "l"(src));
}
#define CP_COMMIT() asm volatile("cp.async.commit_group;" ::: "memory")
#define CP_WAIT(n)  asm volatile("cp.async.wait_group %0;" :: "n"(n) : "memory")

__device__ __forceinline__ void ldm_x4(uint32_t r[4], uint32_t a) {
    asm volatile("ldmatrix.sync.aligned.m8n8.x4.shared.b16 {%0,%1,%2,%3}, [%4];"
                 : "=r"(r[0]), "=r"(r[1]), "=r"(r[2]), "=r"(r[3]) : "r"(a));
}
__device__ __forceinline__ void ldm_x4_t(uint32_t r[4], uint32_t a) {
    asm volatile("ldmatrix.sync.aligned.m8n8.x4.trans.shared.b16 {%0,%1,%2,%3}, [%4];"
                 : "=r"(r[0]), "=r"(r[1]), "=r"(r[2]), "=r"(r[3]) : "r"(a));
}
__device__ __forceinline__ void mma_f16(float c[4], const uint32_t a[4],
                                        uint32_t b0, uint32_t b1) {
    asm volatile(
        "mma.sync.aligned.m16n8k16.row.col.f32.f16.f16.f32 "
        "{%0,%1,%2,%3}, {%4,%5,%6,%7}, {%8,%9}, {%0,%1,%2,%3};"
        : "+f"(c[0]), "+f"(c[1]), "+f"(c[2]), "+f"(c[3])
        : "r"(a[0]), "r"(a[1]), "r"(a[2]), "r"(a[3]), "r"(b0), "r"(b1));
}

__device__ __forceinline__ void split_f16(float v, f16& hi, f16& lo) {
    hi = __float2half(v);
    lo = __float2half(v - __half2float(hi));
}
__device__ __forceinline__ uint32_t pack2h(f16 a, f16 b) {
    __half2 t = {a, b};
    return *(uint32_t*)&t;
}
__device__ __forceinline__ float fast_gelu(float u) {
    float z = 0.7978845608028654f * (u + 0.044715f * u * u * u);
    float t = 1.f - 2.f / (__expf(2.f * z) + 1.f);
    return 0.5f * u * (1.f + t);
}

// ---------------- merged BN stats + segment offsets ----------------
__global__ void bnseg_kernel(const float* __restrict__ s, const float* __restrict__ v,
                             const int* __restrict__ bidx) {
    if (blockIdx.x < 16) {
        int f = blockIdx.x, t = threadIdx.x;
        float sum = 0.f, sq = 0.f;
        for (int i = t; i < NT; i += 256) {
            float x = (f < 13) ? s[i * 13 + f] : v[i * 3 + (f - 13)];
            sum += x; sq += x * x;
        }
        __shared__ float rs[256], rq[256];
        rs[t] = sum; rq[t] = sq;
        __syncthreads();
        for (int st = 128; st > 0; st >>= 1) {
            if (t < st) { rs[t] += rs[t + st]; rq[t] += rq[t + st]; }
            __syncthreads();
        }
        if (t == 0) {
            float m = rs[0] * (1.f / NT);
            float var = rq[0] * (1.f / NT) - m * m;
            g_bn_mean[f] = m;
            g_bn_rstd[f] = rsqrtf(var + EPSV);
        }
    } else {
        int g = threadIdx.x;
        if (g > GN) return;
        int lo = 0, hi = NT;
        while (lo < hi) {
            int mid = (lo + hi) >> 1;
            if (bidx[mid] < g) lo = mid + 1; else hi = mid;
        }
        g_seg[g] = lo;
    }
}

// ---------------- BN + embed + LN1[0], warp per row ----------------
__global__ __launch_bounds__(256)
void embed_ln_kernel(const float* __restrict__ s, const float* __restrict__ v,
                     const float* __restrict__ gamma, const float* __restrict__ beta,
                     const float* __restrict__ w_in, const float* __restrict__ b_in,
                     const float* __restrict__ gam, const float* __restrict__ bet) {
    int w = threadIdx.x >> 5, lane = threadIdx.x & 31;
    int row = blockIdx.x * 8 + w;
    float4 bi = *(const float4*)(b_in + lane * 4);
    float4 gv = *(const float4*)(gam + lane * 4);
    float4 bv = *(const float4*)(bet + lane * 4);
    float xr = 0.f, gmr = 0.f, btr = 0.f, mnr = 0.f, rsr = 0.f;
    if (lane < 16) {
        xr = (lane < 13) ? s[row * 13 + lane] : v[row * 3 + (lane - 13)];
        gmr = gamma[lane]; btr = beta[lane];
        mnr = g_bn_mean[lane]; rsr = g_bn_rstd[lane];
    }
    float xn = (xr - mnr) * rsr * gmr + btr;
    float acc[4] = {bi.x, bi.y, bi.z, bi.w};
#pragma unroll
    for (int k = 0; k < 16; k++) {
        float xk = __shfl_sync(0xffffffffu, xn, k);
        float4 wv = *(const float4*)(w_in + k * DD + lane * 4);
        acc[0] += xk * wv.x; acc[1] += xk * wv.y;
        acc[2] += xk * wv.z; acc[3] += xk * wv.w;
    }
    *(float4*)(g_x + (size_t)row * DD + lane * 4) = *(float4*)acc;
    float ssum = acc[0] + acc[1] + acc[2] + acc[3];
    float sqs = acc[0]*acc[0] + acc[1]*acc[1] + acc[2]*acc[2] + acc[3]*acc[3];
#pragma unroll
    for (int o = 16; o; o >>= 1) {
        ssum += __shfl_xor_sync(0xffffffffu, ssum, o);
        sqs  += __shfl_xor_sync(0xffffffffu, sqs,  o);
    }
    float m = ssum * (1.f / DD);
    float var = sqs * (1.f / DD) - m * m;
    float r = rsqrtf(var + EPSV);
    f16 h[4];
    h[0] = __float2half((acc[0] - m) * r * gv.x + bv.x);
    h[1] = __float2half((acc[1] - m) * r * gv.y + bv.y);
    h[2] = __float2half((acc[2] - m) * r * gv.z + bv.z);
    h[3] = __float2half((acc[3] - m) * r * gv.w + bv.w);
    *(uint2*)(g_y + (size_t)row * DD + lane * 4) = *(uint2*)h;
}

// ---------------- merged weight prep (single fp16) ----------------
#define WQ_E (384 * 128)
#define WO_E (128 * 128)
#define W1_E (512 * 128)
#define W2_E (128 * 512)
__global__ void wprep_kernel(const float* __restrict__ wq, const float* __restrict__ wo,
                             const float* __restrict__ w1, const float* __restrict__ w2) {
    int idx = blockIdx.x * 256 + threadIdx.x;
    const float* w; f16* wd; int K, N, li;
    if (idx < NBLK * WQ_E) {
        w = wq; wd = g_wq; K = 128; N = 384; li = idx;
    } else if (idx < NBLK * (WQ_E + WO_E)) {
        w = wo; wd = g_wo; K = 128; N = 128; li = idx - NBLK * WQ_E;
    } else if (idx < NBLK * (WQ_E + WO_E + W1_E)) {
        w = w1; wd = g_wm1; K = 128; N = 512; li = idx - NBLK * (WQ_E + WO_E);
    } else if (idx < NBLK * (WQ_E + WO_E + W1_E + W2_E)) {
        w = w2; wd = g_wm2; K = 512; N = 128; li = idx - NBLK * (WQ_E + WO_E + W1_E);
    } else return;
    int k = li % K;
    int n = (li / K) % N;
    int b = li / (K * N);
    wd[li] = __float2half(w[(size_t)b * K * N + (size_t)k * N + n]);
}

// ---------------- chunk-pipelined GEMM: plain fp16, 1 MMA ----------------
// C = A(f16) @ W(f16)^T. BM=64, BN=128, 64-K chunks double-buffered.
// 256 threads, 8 warps 2(m) x 4(n), warp tile 32x32.
// Buffer (RS=144): A 64 rows | B 128 rows -> 27648 B.
// FUSE: 2 bias+gelu->f16, 3 bias->hi/lo f16 pair, 4 bias+res->fp32 + LN -> f16
#define RS      144
#define CB_H    9216
#define CBUF    27648
#define GEMM_SMEM (2 * CBUF)   // 55296

template <int FUSE>
__global__ __launch_bounds__(256, 3)
void gemm_mma(const f16* __restrict__ A, const f16* __restrict__ B,
              const float* __restrict__ bias, const float* __restrict__ R,
              float* __restrict__ C, f16* __restrict__ Chi, f16* __restrict__ Clo,
              int K, int Nc,
              const float* __restrict__ lngam, const float* __restrict__ lnbet) {
    extern __shared__ char smem[];
    uint32_t sb = smem_u32(smem);
    int tid = threadIdx.x, lane = tid & 31, wid = tid >> 5;
    int wm = wid & 1, wn = wid >> 1;
    int m0 = blockIdx.y * 64, n0 = blockIdx.x * 128;

    int seg = tid & 7;
    int rowb = tid >> 3;                      // 0..31
    int scol = seg * 16;

    float acc[2][4][4];
#pragma unroll
    for (int i = 0; i < 2; i++)
#pragma unroll
        for (int j = 0; j < 4; j++)
#pragma unroll
            for (int q = 0; q < 4; q++) acc[i][j][q] = 0.f;

    uint32_t a_off = (uint32_t)((wm * 32 + (lane & 15)) * RS + ((lane >> 4) << 4));
    uint32_t b_lane = (uint32_t)((lane & 7) + ((lane >> 4) << 3));
    uint32_t b_half = ((lane >> 3) & 1) << 4;
    uint32_t b_off = (uint32_t)((wn * 32 + b_lane) * RS + b_half);

    int nh = K >> 6;

    // 192 rows x 8 segs; 256 thr -> 6 passes of 32 rows
    auto stage = [&](int h, int b) {
        uint32_t base = sb + (uint32_t)b * CBUF;
        int kc = h << 6;
#pragma unroll
        for (int i = 0; i < 6; i++) {
            int rr = rowb + i * 32;            // 0..191
            uint32_t dst; const f16* src;
            if (rr < 64) {
                dst = base + rr * RS;
                src = A + (size_t)(m0 + rr) * K + kc;
            } else {
                int r = rr - 64;
                dst = base + CB_H + r * RS;
                src = B + (size_t)(n0 + r) * K + kc;
            }
            cp16(dst + scol, (const char*)src + scol);
        }
    };

    stage(0, 0);
    CP_COMMIT();

    for (int h = 0; h < nh; h++) {
        __syncthreads();               // WAR: all warps done with buffer (h+1)&1
        if (h + 1 < nh) stage(h + 1, (h + 1) & 1);
        CP_COMMIT();
        CP_WAIT(1);                    // chunk h landed
        __syncthreads();

        uint32_t base = sb + (uint32_t)(h & 1) * CBUF;
        uint32_t aB = base + a_off;
        uint32_t bB = base + CB_H + b_off;

#pragma unroll
        for (int s = 0; s < 4; s++) {
            uint32_t koff = (uint32_t)(s * 32);
            uint32_t ah[2][4];
#pragma unroll
            for (int mt = 0; mt < 2; mt++)
                ldm_x4(ah[mt], aB + mt * 16 * RS + koff);
            uint32_t bh[4][2];
#pragma unroll
            for (int g4 = 0; g4 < 2; g4++) {
                uint32_t t4[4];
                ldm_x4(t4, bB + g4 * 16 * RS + koff);
                bh[g4 * 2][0] = t4[0]; bh[g4 * 2][1] = t4[1];
                bh[g4 * 2 + 1][0] = t4[2]; bh[g4 * 2 + 1][1] = t4[3];
            }
#pragma unroll
            for (int mt = 0; mt < 2; mt++)
#pragma unroll
                for (int nt = 0; nt < 4; nt++)
                    mma_f16(acc[mt][nt], ah[mt], bh[nt][0], bh[nt][1]);
        }
    }

    float* xbuf = (float*)smem;   // FUSE=4: [64][132] fp32 residual tile
    if (FUSE == 4) __syncthreads();

    int lane4 = lane >> 2, lanem = (lane & 3) * 2;
#pragma unroll
    for (int mt = 0; mt < 2; mt++) {
#pragma unroll
        for (int nt = 0; nt < 4; nt++) {
            int col = n0 + wn * 32 + nt * 8 + lanem;
            int r0 = m0 + wm * 32 + mt * 16 + lane4;
            float2 bb = *(const float2*)(bias + col);
#pragma unroll
            for (int half = 0; half < 2; half++) {
                int r = r0 + half * 8;
                float v0 = acc[mt][nt][half * 2 + 0] + bb.x;
                float v1 = acc[mt][nt][half * 2 + 1] + bb.y;
                size_t o = (size_t)r * Nc + col;
                if (FUSE == 4) {
                    float2 rr = *(const float2*)(R + o);
                    v0 += rr.x; v1 += rr.y;
                    float2 ov = {v0, v1};
                    *(float2*)(C + o) = ov;
                    xbuf[(r - m0) * 132 + col] = v0;
                    xbuf[(r - m0) * 132 + col + 1] = v1;
                } else if (FUSE == 2) {
                    v0 = fast_gelu(v0);
                    v1 = fast_gelu(v1);
                    *(uint32_t*)(Chi + o) = pack2h(__float2half(v0), __float2half(v1));
                } else {  // FUSE == 3: hi/lo pair
                    f16 h0, l0, h1, l1;
                    split_f16(v0, h0, l0);
                    split_f16(v1, h1, l1);
                    *(uint32_t*)(Chi + o) = pack2h(h0, h1);
                    *(uint32_t*)(Clo + o) = pack2h(l0, l1);
                }
            }
        }
    }

    if (FUSE == 4) {
        __syncthreads();
#pragma unroll
        for (int rr = wid; rr < 64; rr += 8) {
            float4 xv = *(float4*)(xbuf + rr * 132 + lane * 4);
            float s = xv.x + xv.y + xv.z + xv.w;
            float sq = xv.x*xv.x + xv.y*xv.y + xv.z*xv.z + xv.w*xv.w;
#pragma unroll
            for (int o = 16; o; o >>= 1) {
                s  += __shfl_xor_sync(0xffffffffu, s,  o);
                sq += __shfl_xor_sync(0xffffffffu, sq, o);
            }
            float m = s * (1.f / DD);
            float var = sq * (1.f / DD) - m * m;
            float rcp = rsqrtf(var + EPSV);
            float4 gv = *(const float4*)(lngam + lane * 4);
            float4 bv = *(const float4*)(lnbet + lane * 4);
            f16 h[4];
            h[0] = __float2half((xv.x - m) * rcp * gv.x + bv.x);
            h[1] = __float2half((xv.y - m) * rcp * gv.y + bv.y);
            h[2] = __float2half((xv.z - m) * rcp * gv.z + bv.z);
            h[3] = __float2half((xv.w - m) * rcp * gv.w + bv.w);
            size_t off = (size_t)(m0 + rr) * DD + lane * 4;
            *(uint2*)(Chi + off) = *(uint2*)h;
        }
    }
}

// ---------------- flash segment attention (fp16 hi/lo 3-term, f16 out) ----------------
#define AT_ROWB 80
#define AT_ARR  (MAXL * AT_ROWB)
#define AT_SMEM (4 * AT_ARR)

__global__ __launch_bounds__(256)
void attn_flash() {
    extern __shared__ char sm[];
    f16* sKh = (f16*)sm;
    f16* sKl = (f16*)(sm + AT_ARR);
    f16* sVh = (f16*)(sm + 2 * AT_ARR);
    f16* sVl = (f16*)(sm + 3 * AT_ARR);

    int g = blockIdx.x, h = blockIdx.y;
    int start = g_seg[g];
    int cnt = g_seg[g + 1] - start;
    if (cnt <= 0) return;
    if (cnt > MAXL) cnt = MAXL;
    int tid = threadIdx.x, lane = tid & 31, wid = tid >> 5;
    int tiles = (cnt + 15) >> 4;
    int ncols = tiles << 4;

    uint32_t aKh = smem_u32(sKh), aKl = smem_u32(sKl);
    uint32_t aVh = smem_u32(sVh), aVl = smem_u32(sVl);

    {
        uint4 z = {0, 0, 0, 0};
        int npad = (ncols - cnt) * 4;
        for (int idx = tid; idx < npad; idx += 256) {
            int j = cnt + (idx >> 2), c = idx & 3;
            int o = j * AT_ROWB + c * 16;
            *(uint4*)((char*)sKh + o) = z;
            *(uint4*)((char*)sKl + o) = z;
            *(uint4*)((char*)sVh + o) = z;
            *(uint4*)((char*)sVl + o) = z;
        }
    }
    for (int idx = tid; idx < cnt * 4; idx += 256) {
        int j = idx >> 2, c = idx & 3;
        size_t base = (size_t)(start + j) * 384 + h * 32 + c * 8;
        uint32_t d = (uint32_t)(j * AT_ROWB + c * 16);
        cp16(aKh + d, g_qh + base + 128);
        cp16(aKl + d, g_ql + base + 128);
        cp16(aVh + d, g_qh + base + 256);
        cp16(aVl + d, g_ql + base + 256);
    }
    CP_COMMIT();
    CP_WAIT(0);
    __syncthreads();

    const float scale = 0.17677669529663687f;
    int fr = lane >> 2, fc = (lane & 3) * 2;
    uint32_t kb_row = (uint32_t)((lane & 7) + ((lane >> 4) << 3));
    uint32_t kb_off = kb_row * AT_ROWB + (((lane >> 3) & 1) << 4);
    uint32_t vt_off = (uint32_t)((lane & 15) * AT_ROWB + ((lane >> 4) << 4));

    for (int mt = wid; mt < tiles; mt += 8) {
        uint32_t qh[2][4], ql[2][4];
        {
            int r1 = start + (mt << 4) + fr, r2 = r1 + 8;
            if (r1 >= NT) r1 = NT - 1;
            if (r2 >= NT) r2 = NT - 1;
            const f16* q1h = g_qh + (size_t)r1 * 384 + h * 32;
            const f16* q2h = g_qh + (size_t)r2 * 384 + h * 32;
            const f16* q1l = g_ql + (size_t)r1 * 384 + h * 32;
            const f16* q2l = g_ql + (size_t)r2 * 384 + h * 32;
#pragma unroll
            for (int ks = 0; ks < 2; ks++) {
                int d0 = ks * 16 + fc, d8 = d0 + 8;
                qh[ks][0] = *(const uint32_t*)(q1h + d0);
                qh[ks][1] = *(const uint32_t*)(q2h + d0);
                qh[ks][2] = *(const uint32_t*)(q1h + d8);
                qh[ks][3] = *(const uint32_t*)(q2h + d8);
                ql[ks][0] = *(const uint32_t*)(q1l + d0);
                ql[ks][1] = *(const uint32_t*)(q2l + d0);
                ql[ks][2] = *(const uint32_t*)(q1l + d8);
                ql[ks][3] = *(const uint32_t*)(q2l + d8);
            }
        }

        float o[4][4];
#pragma unroll
        for (int i = 0; i < 4; i++)
#pragma unroll
            for (int q = 0; q < 4; q++) o[i][q] = 0.f;
        float m_r = -1e30f, m_r8 = -1e30f;
        float l_r = 0.f, l_r8 = 0.f;

        for (int kt = 0; kt < tiles; kt++) {
            float sacc[2][4];
#pragma unroll
            for (int i = 0; i < 2; i++)
#pragma unroll
                for (int q = 0; q < 4; q++) sacc[i][q] = 0.f;
            {
                uint32_t bhf[2][2][2], blf[2][2][2];
#pragma unroll
                for (int ks = 0; ks < 2; ks++) {
                    uint32_t ad = (uint32_t)(kt * 16 * AT_ROWB) + kb_off + ks * 32;
                    uint32_t t4[4];
                    ldm_x4(t4, aKh + ad);
                    bhf[ks][0][0] = t4[0]; bhf[ks][0][1] = t4[1];
                    bhf[ks][1][0] = t4[2]; bhf[ks][1][1] = t4[3];
                    ldm_x4(t4, aKl + ad);
                    blf[ks][0][0] = t4[0]; blf[ks][0][1] = t4[1];
                    blf[ks][1][0] = t4[2]; blf[ks][1][1] = t4[3];
                }
#pragma unroll
                for (int ks = 0; ks < 2; ks++) {
#pragma unroll
                    for (int n8 = 0; n8 < 2; n8++)
                        mma_f16(sacc[n8], qh[ks], bhf[ks][n8][0], bhf[ks][n8][1]);
#pragma unroll
                    for (int n8 = 0; n8 < 2; n8++)
                        mma_f16(sacc[n8], qh[ks], blf[ks][n8][0], blf[ks][n8][1]);
#pragma unroll
                    for (int n8 = 0; n8 < 2; n8++)
                        mma_f16(sacc[n8], ql[ks], bhf[ks][n8][0], bhf[ks][n8][1]);
                }
            }
            float sv[2][4];
#pragma unroll
            for (int n8 = 0; n8 < 2; n8++)
#pragma unroll
                for (int q = 0; q < 4; q++) {
                    int col = kt * 16 + n8 * 8 + fc + (q & 1);
                    sv[n8][q] = (col < cnt) ? sacc[n8][q] * scale : -1e30f;
                }
            float tm_r  = fmaxf(fmaxf(sv[0][0], sv[0][1]), fmaxf(sv[1][0], sv[1][1]));
            float tm_r8 = fmaxf(fmaxf(sv[0][2], sv[0][3]), fmaxf(sv[1][2], sv[1][3]));
#pragma unroll
            for (int oX = 1; oX <= 2; oX <<= 1) {
                tm_r  = fmaxf(tm_r,  __shfl_xor_sync(0xffffffffu, tm_r,  oX));
                tm_r8 = fmaxf(tm_r8, __shfl_xor_sync(0xffffffffu, tm_r8, oX));
            }
            float Mn_r = fmaxf(m_r, tm_r), Mn_r8 = fmaxf(m_r8, tm_r8);
            float cr = __expf(m_r - Mn_r), cr8 = __expf(m_r8 - Mn_r8);
            m_r = Mn_r; m_r8 = Mn_r8;
            float p[2][4];
#pragma unroll
            for (int n8 = 0; n8 < 2; n8++) {
                p[n8][0] = __expf(sv[n8][0] - Mn_r);
                p[n8][1] = __expf(sv[n8][1] - Mn_r);
                p[n8][2] = __expf(sv[n8][2] - Mn_r8);
                p[n8][3] = __expf(sv[n8][3] - Mn_r8);
            }
            l_r  = l_r  * cr  + p[0][0] + p[0][1] + p[1][0] + p[1][1];
            l_r8 = l_r8 * cr8 + p[0][2] + p[0][3] + p[1][2] + p[1][3];
#pragma unroll
            for (int nn = 0; nn < 4; nn++) {
                o[nn][0] *= cr;  o[nn][1] *= cr;
                o[nn][2] *= cr8; o[nn][3] *= cr8;
            }
            uint32_t pa[4], pl[4];
            {
                f16 h0, l0, h1, l1;
                split_f16(p[0][0], h0, l0); split_f16(p[0][1], h1, l1);
                pa[0] = pack2h(h0, h1); pl[0] = pack2h(l0, l1);
                split_f16(p[0][2], h0, l0); split_f16(p[0][3], h1, l1);
                pa[1] = pack2h(h0, h1); pl[1] = pack2h(l0, l1);
                split_f16(p[1][0], h0, l0); split_f16(p[1][1], h1, l1);
                pa[2] = pack2h(h0, h1); pl[2] = pack2h(l0, l1);
                split_f16(p[1][2], h0, l0); split_f16(p[1][3], h1, l1);
                pa[3] = pack2h(h0, h1); pl[3] = pack2h(l0, l1);
            }
            uint32_t vhf[4][2], vlf[4][2];
#pragma unroll
            for (int cc = 0; cc < 2; cc++) {
                uint32_t ad = (uint32_t)(kt * 16 * AT_ROWB) + vt_off + cc * 32;
                uint32_t t4[4];
                ldm_x4_t(t4, aVh + ad);
                vhf[cc * 2][0] = t4[0]; vhf[cc * 2][1] = t4[1];
                vhf[cc * 2 + 1][0] = t4[2]; vhf[cc * 2 + 1][1] = t4[3];
                ldm_x4_t(t4, aVl + ad);
                vlf[cc * 2][0] = t4[0]; vlf[cc * 2][1] = t4[1];
                vlf[cc * 2 + 1][0] = t4[2]; vlf[cc * 2 + 1][1] = t4[3];
            }
#pragma unroll
            for (int nn = 0; nn < 4; nn++)
                mma_f16(o[nn], pa, vhf[nn][0], vhf[nn][1]);
#pragma unroll
            for (int nn = 0; nn < 4; nn++)
                mma_f16(o[nn], pa, vlf[nn][0], vlf[nn][1]);
#pragma unroll
            for (int nn = 0; nn < 4; nn++)
                mma_f16(o[nn], pl, vhf[nn][0], vhf[nn][1]);
        }

#pragma unroll
        for (int oX = 1; oX <= 2; oX <<= 1) {
            l_r  += __shfl_xor_sync(0xffffffffu, l_r,  oX);
            l_r8 += __shfl_xor_sync(0xffffffffu, l_r8, oX);
        }
        float i1 = 1.f / l_r, i2 = 1.f / l_r8;
        int lr1 = (mt << 4) + fr, lr2 = lr1 + 8;
#pragma unroll
        for (int nn = 0; nn < 4; nn++) {
            int col = h * 32 + nn * 8 + fc;
            if (lr1 < cnt) {
                size_t off = (size_t)(start + lr1) * DD + col;
                *(uint32_t*)(g_a + off) =
                    pack2h(__float2half(o[nn][0] * i1), __float2half(o[nn][1] * i1));
            }
            if (lr2 < cnt) {
                size_t off = (size_t)(start + lr2) * DD + col;
                *(uint32_t*)(g_a + off) =
                    pack2h(__float2half(o[nn][2] * i2), __float2half(o[nn][3] * i2));
            }
        }
    }
}

// ---------------- final projection: warp per row ----------------
__global__ __launch_bounds__(256)
void out_kernel(const float* __restrict__ w_out, const float* __restrict__ b_out,
                float* __restrict__ out) {
    int w = threadIdx.x >> 5, lane = threadIdx.x & 31;
    int row = blockIdx.x * 8 + w;
    size_t base = (size_t)row * DD + lane * 4;
    uint2 hx = *(const uint2*)(g_y + base);
    float x[4];
#pragma unroll
    for (int j = 0; j < 4; j++)
        x[j] = __half2float(((f16*)&hx)[j]);
    float p0 = 0.f, p1 = 0.f, p2 = 0.f, p3 = 0.f;
#pragma unroll
    for (int j = 0; j < 4; j++) {
        int t = lane * 4 + j;
        float4 wv = *(const float4*)(w_out + t * 4);
        p0 += x[j] * wv.x; p1 += x[j] * wv.y;
        p2 += x[j] * wv.z; p3 += x[j] * wv.w;
    }
#pragma unroll
    for (int o = 16; o; o >>= 1) {
        p0 += __shfl_xor_sync(0xffffffffu, p0, o);
        p1 += __shfl_xor_sync(0xffffffffu, p1, o);
        p2 += __shfl_xor_sync(0xffffffffu, p2, o);
        p3 += __shfl_xor_sync(0xffffffffu, p3, o);
    }
    if (lane == 0) {
        float4 ov;
        ov.x = p0 + b_out[0];
        ov.y = p1 + b_out[1];
        ov.z = p2 + b_out[2];
        float v3 = p3 + b_out[3];
        ov.w = 1.f / (1.f + __expf(-v3));
        *(float4*)(out + (size_t)row * 4) = ov;
    }
}

// ---------------- launcher ----------------
extern "C" void kernel_launch(void* const* d_in, const int* in_sizes, int n_in,
                              void* d_out, int out_size) {
    const float* inputs_scalar = (const float*)d_in[0];
    const float* inputs_v      = (const float*)d_in[1];
    const int*   batch_idx     = (const int*)  d_in[2];
    const float* bn_gamma      = (const float*)d_in[3];
    const float* bn_beta       = (const float*)d_in[4];
    const float* w_in          = (const float*)d_in[5];
    const float* b_in          = (const float*)d_in[6];
    const float* ln1_g         = (const float*)d_in[7];
    const float* ln1_b         = (const float*)d_in[8];
    const float* w_qkv         = (const float*)d_in[9];
    const float* b_qkv         = (const float*)d_in[10];
    const float* w_o           = (const float*)d_in[11];
    const float* b_o           = (const float*)d_in[12];
    const float* ln2_g         = (const float*)d_in[13];
    const float* ln2_b         = (const float*)d_in[14];
    const float* w_m1          = (const float*)d_in[15];
    const float* b_m1          = (const float*)d_in[16];
    const float* w_m2          = (const float*)d_in[17];
    const float* b_m2          = (const float*)d_in[18];
    const float* lnf_g         = (const float*)d_in[19];
    const float* lnf_b         = (const float*)d_in[20];
    const float* w_out         = (const float*)d_in[21];
    const float* b_out         = (const float*)d_in[22];
    float* out = (float*)d_out;

    (void)in_sizes; (void)n_in; (void)out_size;

    cudaFuncSetAttribute(attn_flash, cudaFuncAttributeMaxDynamicSharedMemorySize, AT_SMEM);
    cudaFuncSetAttribute(gemm_mma<2>, cudaFuncAttributeMaxDynamicSharedMemorySize, GEMM_SMEM);
    cudaFuncSetAttribute(gemm_mma<3>, cudaFuncAttributeMaxDynamicSharedMemorySize, GEMM_SMEM);
    cudaFuncSetAttribute(gemm_mma<4>, cudaFuncAttributeMaxDynamicSharedMemorySize, GEMM_SMEM);

    float* px;
    f16 *qh, *ql, *py, *pa, *pm;
    cudaGetSymbolAddress((void**)&px, g_x);
    cudaGetSymbolAddress((void**)&qh, g_qh);
    cudaGetSymbolAddress((void**)&ql, g_ql);
    cudaGetSymbolAddress((void**)&py, g_y);
    cudaGetSymbolAddress((void**)&pa, g_a);
    cudaGetSymbolAddress((void**)&pm, g_m);
    f16 *wq, *wo, *w1, *w2;
    cudaGetSymbolAddress((void**)&wq, g_wq);
    cudaGetSymbolAddress((void**)&wo, g_wo);
    cudaGetSymbolAddress((void**)&w1, g_wm1);
    cudaGetSymbolAddress((void**)&w2, g_wm2);

    int wtotal = NBLK * (WQ_E + WO_E + W1_E + W2_E);
    wprep_kernel<<<(wtotal + 255) / 256, 256>>>(w_qkv, w_o, w_m1, w_m2);

    bnseg_kernel<<<17, 256>>>(inputs_scalar, inputs_v, batch_idx);
    embed_ln_kernel<<<NT / 8, 256>>>(inputs_scalar, inputs_v, bn_gamma, bn_beta,
                                     w_in, b_in, ln1_g, ln1_b);

    for (int i = 0; i < NBLK; i++) {
        gemm_mma<3><<<dim3(3, NT / 64), 256, GEMM_SMEM>>>(
            py, wq + (size_t)i * WQ_E,
            b_qkv + i * 3 * DD, nullptr, nullptr, qh, ql, 128, 384, nullptr, nullptr);
        attn_flash<<<dim3(GN, HN), 256, AT_SMEM>>>();
        gemm_mma<4><<<dim3(1, NT / 64), 256, GEMM_SMEM>>>(
            pa, wo + (size_t)i * WO_E,
            b_o + i * DD, px, px, py, nullptr, 128, 128,
            ln2_g + i * DD, ln2_b + i * DD);
        gemm_mma<2><<<dim3(4, NT / 64), 256, GEMM_SMEM>>>(
            py, w1 + (size_t)i * W1_E,
            b_m1 + i * 4 * DD, nullptr, nullptr, pm, nullptr, 128, 512, nullptr, nullptr);
        const float* ng = (i + 1 < NBLK) ? (ln1_g + (i + 1) * DD) : lnf_g;
        const float* nb = (i + 1 < NBLK) ? (ln1_b + (i + 1) * DD) : lnf_b;
        gemm_mma<4><<<dim3(1, NT / 64), 256, GEMM_SMEM>>>(
            pm, w2 + (size_t)i * W2_E,
            b_m2 + i * DD, px, px, py, nullptr, 512, 128, ng, nb);
    }

    out_kernel<<<NT / 8, 256>>>(w_out, b_out, out);
}